// round 3
// baseline (speedup 1.0000x reference)
#include <cuda_runtime.h>
#include <cuda_bf16.h>
#include <math.h>

// Problem constants (fixed by reference setup_inputs):
// B=64, C=20, K=5, Q=15, D=H=2048
// support [6400, 2048], query [19200, 2048], onehot [64,100,20], W [2048,2048], b[2048]
#define D_DIM 2048
#define NSUP  6400     // B*C*K
#define NQRY  19200    // B*C*Q
#define NEP   64       // episodes
#define SPE   100      // support per episode (C*K)
#define QPE   300      // queries per episode (C*Q)
#define NCLS  20

// Scratch (device globals: allocation-free per harness rules)
__device__ float g_s[NSUP * D_DIM];    // encoded support  (52.4 MB)
__device__ float g_q[NQRY * D_DIM];    // encoded query    (157.3 MB)
__device__ float g_inv[NSUP];          // inv support norms

// ---------------------------------------------------------------------------
// SGEMM: out[M, 2048] = X[M, 2048] @ W[2048, 2048] + b
// 128x128 block tile, 8x8 per thread, BK=8, 256 threads.
// M, N, K all multiples of tile sizes -> no bounds checks.
// ---------------------------------------------------------------------------
#define BM 128
#define BN 128
#define BK 8
#define TM 8
#define TN 8

__global__ __launch_bounds__(256, 2)
void sgemm_bias(const float* __restrict__ A, const float* __restrict__ B,
                const float* __restrict__ bias, float* __restrict__ C) {
    const int N = D_DIM, K = D_DIM;
    __shared__ __align__(16) float As[BK][BM];
    __shared__ __align__(16) float Bs[BK][BN];

    const int bx = blockIdx.x;   // N tile
    const int by = blockIdx.y;   // M tile
    const int tid = threadIdx.x; // 0..255
    const int tx = tid % 16;
    const int ty = tid / 16;

    // global load indices
    const int arow = tid >> 1;          // 0..127
    const int acol = (tid & 1) * 4;     // 0 or 4
    const int brow = tid >> 5;          // 0..7
    const int bcol = (tid & 31) * 4;    // 0..124

    const float* Ab = A + (size_t)(by * BM) * K;
    const float* Bb = B + bx * BN;

    float acc[TM][TN];
#pragma unroll
    for (int i = 0; i < TM; i++)
#pragma unroll
        for (int j = 0; j < TN; j++) acc[i][j] = 0.0f;

    for (int k0 = 0; k0 < K; k0 += BK) {
        float4 a4 = *(const float4*)(Ab + (size_t)arow * K + k0 + acol);
        As[acol + 0][arow] = a4.x;
        As[acol + 1][arow] = a4.y;
        As[acol + 2][arow] = a4.z;
        As[acol + 3][arow] = a4.w;
        float4 b4 = *(const float4*)(Bb + (size_t)(k0 + brow) * N + bcol);
        *(float4*)(&Bs[brow][bcol]) = b4;
        __syncthreads();

#pragma unroll
        for (int kk = 0; kk < BK; kk++) {
            float4 a0 = *(const float4*)(&As[kk][ty * TM]);
            float4 a1 = *(const float4*)(&As[kk][ty * TM + 4]);
            float4 b0 = *(const float4*)(&Bs[kk][tx * TN]);
            float4 b1 = *(const float4*)(&Bs[kk][tx * TN + 4]);
            float ra[TM] = {a0.x, a0.y, a0.z, a0.w, a1.x, a1.y, a1.z, a1.w};
            float rb[TN] = {b0.x, b0.y, b0.z, b0.w, b1.x, b1.y, b1.z, b1.w};
#pragma unroll
            for (int i = 0; i < TM; i++)
#pragma unroll
                for (int j = 0; j < TN; j++)
                    acc[i][j] = fmaf(ra[i], rb[j], acc[i][j]);
        }
        __syncthreads();
    }

    // epilogue: add bias, store
#pragma unroll
    for (int i = 0; i < TM; i++) {
        const int row = by * BM + ty * TM + i;
#pragma unroll
        for (int j = 0; j < TN; j += 4) {
            const int col = bx * BN + tx * TN + j;
            float4 v;
            v.x = acc[i][j + 0] + bias[col + 0];
            v.y = acc[i][j + 1] + bias[col + 1];
            v.z = acc[i][j + 2] + bias[col + 2];
            v.w = acc[i][j + 3] + bias[col + 3];
            *(float4*)(&C[(size_t)row * N + col]) = v;
        }
    }
}

// ---------------------------------------------------------------------------
// inv_norm[row] = rsqrt(max(sum(s[row]^2), 1e-10))
// ---------------------------------------------------------------------------
__global__ void rownorm_kernel(const float* __restrict__ s, float* __restrict__ inv) {
    const int row = blockIdx.x;
    const float* p = s + (size_t)row * D_DIM;
    float sum = 0.0f;
    for (int k = threadIdx.x; k < D_DIM; k += 256) {
        float v = p[k];
        sum = fmaf(v, v, sum);
    }
    // warp reduce
#pragma unroll
    for (int off = 16; off > 0; off >>= 1)
        sum += __shfl_down_sync(0xFFFFFFFF, sum, off);
    __shared__ float warpsum[8];
    const int lane = threadIdx.x & 31, wid = threadIdx.x >> 5;
    if (lane == 0) warpsum[wid] = sum;
    __syncthreads();
    if (threadIdx.x == 0) {
        float t = 0.0f;
#pragma unroll
        for (int w = 0; w < 8; w++) t += warpsum[w];
        inv[row] = rsqrtf(fmaxf(t, 1e-10f));
    }
}

// ---------------------------------------------------------------------------
// Fused attention: per (episode, 30-query-row tile):
//   sim = q_tile @ s_ep^T * inv_norm  -> softmax over 100 -> label buckets
// blockDim = 160 (150 active for GEMM: 6 row-groups x 25 col-groups, 5x4 tile)
// ---------------------------------------------------------------------------
#define TQ 30
#define KC 32

__global__ __launch_bounds__(160)
void attention_kernel(const float* __restrict__ onehot,
                      float* __restrict__ out, int out_size) {
    __shared__ __align__(16) float qs[TQ][KC + 1];     // 30x33
    __shared__ __align__(16) float ssT[KC][SPE + 4];   // 32x104 (transposed s tile)
    __shared__ __align__(16) float simT[TQ][SPE];      // 30x100
    __shared__ float invn[SPE];
    __shared__ int   lab[SPE];
    __shared__ float probsS[TQ][NCLS];

    const int t = blockIdx.x;   // 0..9 query tile within episode
    const int e = blockIdx.y;   // 0..63 episode
    const int tid = threadIdx.x;
    const int qbase = e * QPE + t * TQ;
    const int sbase = e * SPE;

    if (tid < SPE) {
        invn[tid] = g_inv[sbase + tid];
        const float* oh = onehot + (size_t)(e * SPE + tid) * NCLS;
        int l = 0;
        float best = oh[0];
#pragma unroll
        for (int c = 1; c < NCLS; c++) {
            float v = oh[c];
            if (v > best) { best = v; l = c; }
        }
        lab[tid] = l;
    }

    const int rg = tid / 25;     // 0..5 valid
    const int cg = tid % 25;     // 0..24
    const bool active = tid < 150;

    float acc[5][4];
#pragma unroll
    for (int ii = 0; ii < 5; ii++)
#pragma unroll
        for (int jj = 0; jj < 4; jj++) acc[ii][jj] = 0.0f;

    for (int k0 = 0; k0 < D_DIM; k0 += KC) {
        __syncthreads();
        // load q tile [30][32]
        for (int idx = tid; idx < TQ * KC; idx += 160) {
            int i = idx / KC, kc = idx % KC;
            qs[i][kc] = g_q[(size_t)(qbase + i) * D_DIM + k0 + kc];
        }
        // load s tile transposed [32][100]
        for (int idx = tid; idx < SPE * KC; idx += 160) {
            int r = idx / KC, kc = idx % KC;
            ssT[kc][r] = g_s[(size_t)(sbase + r) * D_DIM + k0 + kc];
        }
        __syncthreads();
        if (active) {
#pragma unroll 4
            for (int kc = 0; kc < KC; kc++) {
                float4 sv = *(const float4*)(&ssT[kc][cg * 4]);
                float q0 = qs[rg * 5 + 0][kc];
                float q1 = qs[rg * 5 + 1][kc];
                float q2 = qs[rg * 5 + 2][kc];
                float q3 = qs[rg * 5 + 3][kc];
                float q4 = qs[rg * 5 + 4][kc];
                acc[0][0] = fmaf(q0, sv.x, acc[0][0]);
                acc[0][1] = fmaf(q0, sv.y, acc[0][1]);
                acc[0][2] = fmaf(q0, sv.z, acc[0][2]);
                acc[0][3] = fmaf(q0, sv.w, acc[0][3]);
                acc[1][0] = fmaf(q1, sv.x, acc[1][0]);
                acc[1][1] = fmaf(q1, sv.y, acc[1][1]);
                acc[1][2] = fmaf(q1, sv.z, acc[1][2]);
                acc[1][3] = fmaf(q1, sv.w, acc[1][3]);
                acc[2][0] = fmaf(q2, sv.x, acc[2][0]);
                acc[2][1] = fmaf(q2, sv.y, acc[2][1]);
                acc[2][2] = fmaf(q2, sv.z, acc[2][2]);
                acc[2][3] = fmaf(q2, sv.w, acc[2][3]);
                acc[3][0] = fmaf(q3, sv.x, acc[3][0]);
                acc[3][1] = fmaf(q3, sv.y, acc[3][1]);
                acc[3][2] = fmaf(q3, sv.z, acc[3][2]);
                acc[3][3] = fmaf(q3, sv.w, acc[3][3]);
                acc[4][0] = fmaf(q4, sv.x, acc[4][0]);
                acc[4][1] = fmaf(q4, sv.y, acc[4][1]);
                acc[4][2] = fmaf(q4, sv.z, acc[4][2]);
                acc[4][3] = fmaf(q4, sv.w, acc[4][3]);
            }
        }
    }
    __syncthreads();
    if (active) {
#pragma unroll
        for (int ii = 0; ii < 5; ii++)
#pragma unroll
            for (int jj = 0; jj < 4; jj++)
                simT[rg * 5 + ii][cg * 4 + jj] = acc[ii][jj] * invn[cg * 4 + jj];
    }
    __syncthreads();

    // softmax + label-bucketed prediction, one thread per query row
    if (tid < TQ) {
        const int row = tid;
        float m = -1e30f;
#pragma unroll 4
        for (int ss = 0; ss < SPE; ss++) m = fmaxf(m, simT[row][ss]);
        float* p = probsS[row];
#pragma unroll
        for (int c = 0; c < NCLS; c++) p[c] = 0.0f;
        float sum = 0.0f;
        for (int ss = 0; ss < SPE; ss++) {
            float w = expf(simT[row][ss] - m);
            sum += w;
            p[lab[ss]] += w;
        }
        const float invsum = 1.0f / sum;
        const int grow = qbase + row;
        int bestc = 0;
        float bestv = p[0];
#pragma unroll
        for (int c = 0; c < NCLS; c++) {
            float v = p[c] * invsum;
            out[(size_t)grow * NCLS + c] = v;
            if (p[c] > bestv) { bestv = p[c]; bestc = c; }
        }
        // optional second output: argmax predictions (as output dtype)
        if (out_size >= NQRY * NCLS + NQRY)
            out[NQRY * NCLS + grow] = (float)bestc;
    }
}

// ---------------------------------------------------------------------------
extern "C" void kernel_launch(void* const* d_in, const int* in_sizes, int n_in,
                              void* d_out, int out_size) {
    const float* support = (const float*)d_in[0];
    const float* query   = (const float*)d_in[1];
    const float* onehot  = (const float*)d_in[2];
    const float* W       = (const float*)d_in[3];
    const float* b       = (const float*)d_in[4];
    float* out = (float*)d_out;

    float *ps, *pq, *pinv;
    cudaGetSymbolAddress((void**)&ps, g_s);
    cudaGetSymbolAddress((void**)&pq, g_q);
    cudaGetSymbolAddress((void**)&pinv, g_inv);

    // encoder GEMMs
    dim3 gs(D_DIM / BN, NSUP / BM);
    sgemm_bias<<<gs, 256>>>(support, W, b, ps);
    dim3 gq(D_DIM / BN, NQRY / BM);
    sgemm_bias<<<gq, 256>>>(query, W, b, pq);

    // support inverse norms
    rownorm_kernel<<<NSUP, 256>>>(ps, pinv);

    // fused attention / softmax / classify
    dim3 ga(QPE / TQ, NEP);
    attention_kernel<<<ga, 160>>>(onehot, out, out_size);
}

// round 6
// speedup vs baseline: 2.4658x; 2.4658x over previous
#include <cuda_runtime.h>
#include <cuda_bf16.h>
#include <math.h>
#include <stdint.h>

// Problem constants (fixed by reference setup_inputs):
// B=64, C=20, K=5, Q=15, D=H=2048
#define D_DIM 2048
#define NSUP  6400
#define NQRY  19200
#define NEP   64
#define SPE   100
#define QPE   300
#define NCLS  20

// Scratch (device globals: allocation-free per harness rules)
__device__ float g_s[NSUP * D_DIM];                 // encoded support
__device__ float g_q[NQRY * D_DIM];                 // encoded query
__device__ float g_inv[NSUP];                       // inv support norms
__device__ __nv_bfloat16 g_wt_hi[D_DIM * D_DIM];    // W^T split hi (bf16), [n][k]
__device__ __nv_bfloat16 g_wt_lo[D_DIM * D_DIM];    // W^T split lo (bf16), [n][k]

// ---------------------------------------------------------------------------
// Helpers (plain sm_80+ PTX only: ldmatrix / mma.sync / cp.async — all legal
// at compute_103 non-'a' target)
// ---------------------------------------------------------------------------
__device__ __forceinline__ uint32_t smem_u32(const void* p) {
    uint32_t a;
    asm("{ .reg .u64 t; cvta.to.shared.u64 t, %1; cvt.u32.u64 %0, t; }" : "=r"(a) : "l"(p));
    return a;
}

__device__ __forceinline__ void ldsm4(uint32_t* r, uint32_t addr) {
    asm volatile("ldmatrix.sync.aligned.m8n8.x4.shared.b16 {%0,%1,%2,%3}, [%4];"
                 : "=r"(r[0]), "=r"(r[1]), "=r"(r[2]), "=r"(r[3]) : "r"(addr));
}

__device__ __forceinline__ void mma_bf16(float* d, const uint32_t* a, uint32_t b0, uint32_t b1) {
    asm volatile("mma.sync.aligned.m16n8k16.row.col.f32.bf16.bf16.f32 "
                 "{%0,%1,%2,%3}, {%4,%5,%6,%7}, {%8,%9}, {%0,%1,%2,%3};"
                 : "+f"(d[0]), "+f"(d[1]), "+f"(d[2]), "+f"(d[3])
                 : "r"(a[0]), "r"(a[1]), "r"(a[2]), "r"(a[3]), "r"(b0), "r"(b1));
}

__device__ __forceinline__ void cp_async16(uint32_t dst, const void* src) {
    asm volatile("cp.async.ca.shared.global [%0], [%1], 16;" :: "r"(dst), "l"(src));
}
#define CP_COMMIT() asm volatile("cp.async.commit_group;" ::: "memory")
#define CP_WAIT0()  asm volatile("cp.async.wait_group 0;"  ::: "memory")

// ---------------------------------------------------------------------------
// W transpose + split into bf16 hi/lo:  Wt[n][k] = W[k][n] = hi + lo
// ---------------------------------------------------------------------------
__global__ __launch_bounds__(256)
void wsplit_kernel(const float* __restrict__ W,
                   __nv_bfloat16* __restrict__ Whi, __nv_bfloat16* __restrict__ Wlo) {
    __shared__ float t[32][33];
    const int tx = threadIdx.x & 31, ty = threadIdx.x >> 5;
    const int kb = blockIdx.y * 32, nb = blockIdx.x * 32;
#pragma unroll
    for (int i = 0; i < 4; i++) {
        int kr = ty + i * 8;
        t[kr][tx] = W[(size_t)(kb + kr) * D_DIM + nb + tx];
    }
    __syncthreads();
#pragma unroll
    for (int i = 0; i < 4; i++) {
        int n = nb + ty + i * 8;
        int k = kb + tx;
        float v = t[tx][ty + i * 8];
        __nv_bfloat16 h = __float2bfloat16_rn(v);
        float r = v - __bfloat162float(h);
        Whi[(size_t)n * D_DIM + k] = h;
        Wlo[(size_t)n * D_DIM + k] = __float2bfloat16_rn(r);
    }
}

// ---------------------------------------------------------------------------
// Tensor-core GEMM via mma.sync (HMMA): C[M,2048] = A[M,2048] @ W + b
// split-bf16 3-term, fp32 accumulators.
// BM=128, BN=256, BK=32. 512 threads = 16 warps, warp tile 64x32.
// Smem rows padded to 80B -> conflict-free ldmatrix.
// ---------------------------------------------------------------------------
#define GK 2048
#define BKC 32                      // k per chunk
#define NCHUNK (GK / BKC)           // 64
#define ROWB 80                     // smem row stride bytes (32 bf16 = 64B + pad)
#define OFF_AHI 0
#define OFF_ALO (128 * ROWB)        // 10240
#define OFF_BHI (2 * 128 * ROWB)    // 20480
#define OFF_BLO (OFF_BHI + 256 * ROWB)
#define STAGEB  (OFF_BLO + 256 * ROWB)   // 61440
#define GEMM_SMEM (2 * STAGEB)           // 122880

__global__ __launch_bounds__(512, 1)
void gemm_mma(const float* __restrict__ A,
              const __nv_bfloat16* __restrict__ Bhi, const __nv_bfloat16* __restrict__ Blo,
              const float* __restrict__ bias, float* __restrict__ C) {
    extern __shared__ __align__(128) char smem[];
    const uint32_t sb = smem_u32(smem);
    const int tid = threadIdx.x;
    const int lane = tid & 31, warp = tid >> 5;
    const int wm = warp & 1;        // 0..1 -> m offset 64
    const int wn = warp >> 1;       // 0..7 -> n offset 32
    const int bx = blockIdx.x, by = blockIdx.y;

    const float* Ab = A + (size_t)(by * 128) * GK;
    const size_t bn0 = (size_t)(bx * 256);

    // ---- fill task indices ----
    // A: 1024 tasks (128 rows x 8 float4-chunks); 2 per thread
    const int ar0 = tid >> 3, ac0 = (tid & 7);
    const int ar1 = (tid + 512) >> 3, ac1 = ((tid + 512) & 7);
    // B: 1024 tasks (256 rows x 4 x16B chunks) per (hi,lo); 2 per thread
    const int br0 = tid >> 2, bc0 = (tid & 3);
    const int br1 = (tid + 512) >> 2, bc1 = ((tid + 512) & 3);

    float4 a0, a1;   // prefetch regs

    // ---- helpers as lambdas ----
    auto loadA = [&](int k0) {
        a0 = *(const float4*)(Ab + (size_t)ar0 * GK + k0 + ac0 * 4);
        a1 = *(const float4*)(Ab + (size_t)ar1 * GK + k0 + ac1 * 4);
    };
    auto storeA = [&](uint32_t stage) {
        __nv_bfloat162 h01 = __floats2bfloat162_rn(a0.x, a0.y);
        __nv_bfloat162 h23 = __floats2bfloat162_rn(a0.z, a0.w);
        __nv_bfloat162 l01 = __floats2bfloat162_rn(a0.x - __low2float(h01), a0.y - __high2float(h01));
        __nv_bfloat162 l23 = __floats2bfloat162_rn(a0.z - __low2float(h23), a0.w - __high2float(h23));
        uint32_t off = stage + ar0 * ROWB + ac0 * 8;
        *(uint2*)(smem + (off - sb) + OFF_AHI) = make_uint2(*(uint32_t*)&h01, *(uint32_t*)&h23);
        *(uint2*)(smem + (off - sb) + OFF_ALO) = make_uint2(*(uint32_t*)&l01, *(uint32_t*)&l23);
        __nv_bfloat162 H01 = __floats2bfloat162_rn(a1.x, a1.y);
        __nv_bfloat162 H23 = __floats2bfloat162_rn(a1.z, a1.w);
        __nv_bfloat162 L01 = __floats2bfloat162_rn(a1.x - __low2float(H01), a1.y - __high2float(H01));
        __nv_bfloat162 L23 = __floats2bfloat162_rn(a1.z - __low2float(H23), a1.w - __high2float(H23));
        uint32_t off1 = stage + ar1 * ROWB + ac1 * 8;
        *(uint2*)(smem + (off1 - sb) + OFF_AHI) = make_uint2(*(uint32_t*)&H01, *(uint32_t*)&H23);
        *(uint2*)(smem + (off1 - sb) + OFF_ALO) = make_uint2(*(uint32_t*)&L01, *(uint32_t*)&L23);
    };
    auto loadB = [&](int k0, uint32_t stage) {
        const __nv_bfloat16* h0 = Bhi + (bn0 + br0) * GK + k0 + bc0 * 8;
        const __nv_bfloat16* l0 = Blo + (bn0 + br0) * GK + k0 + bc0 * 8;
        const __nv_bfloat16* h1 = Bhi + (bn0 + br1) * GK + k0 + bc1 * 8;
        const __nv_bfloat16* l1 = Blo + (bn0 + br1) * GK + k0 + bc1 * 8;
        cp_async16(stage + OFF_BHI + br0 * ROWB + bc0 * 16, h0);
        cp_async16(stage + OFF_BLO + br0 * ROWB + bc0 * 16, l0);
        cp_async16(stage + OFF_BHI + br1 * ROWB + bc1 * 16, h1);
        cp_async16(stage + OFF_BLO + br1 * ROWB + bc1 * 16, l1);
        CP_COMMIT();
    };

    // ---- ldmatrix lane addressing (relative to stage base) ----
    // A: row = wm*64 + mi*16 + (lane&15); koff = (lane>>4)*16 + kk*32
    const uint32_t a_lane_off = (uint32_t)((wm * 64 + (lane & 15)) * ROWB + (lane >> 4) * 16);
    // B: n = wn*32 + nj*16 + ((lane>>4)<<3) + (lane&7); koff = ((lane>>3)&1)*16 + kk*32
    const uint32_t b_lane_off = (uint32_t)((wn * 32 + ((lane >> 4) << 3) + (lane & 7)) * ROWB
                                           + ((lane >> 3) & 1) * 16);

    float acc[4][4][4];
#pragma unroll
    for (int mi = 0; mi < 4; mi++)
#pragma unroll
        for (int ni = 0; ni < 4; ni++)
#pragma unroll
            for (int j = 0; j < 4; j++) acc[mi][ni][j] = 0.0f;

    // ---- prologue: chunk 0 ----
    loadA(0);
    loadB(0, sb);
    storeA(sb);
    CP_WAIT0();
    __syncthreads();

    for (int c = 0; c < NCHUNK; c++) {
        const uint32_t stage = sb + (uint32_t)((c & 1) * STAGEB);
        const uint32_t next  = sb + (uint32_t)(((c + 1) & 1) * STAGEB);
        const bool more = (c + 1 < NCHUNK);
        if (more) {
            loadA((c + 1) * BKC);
            loadB((c + 1) * BKC, next);
        }

#pragma unroll
        for (int kk = 0; kk < 2; kk++) {
            const uint32_t kb = kk * 32;
            uint32_t ah[4][4], al[4][4], bh[2][4], bl[2][4];
#pragma unroll
            for (int mi = 0; mi < 4; mi++)
                ldsm4(ah[mi], stage + OFF_AHI + a_lane_off + mi * (16 * ROWB) + kb);
#pragma unroll
            for (int nj = 0; nj < 2; nj++) {
                ldsm4(bh[nj], stage + OFF_BHI + b_lane_off + nj * (16 * ROWB) + kb);
                ldsm4(bl[nj], stage + OFF_BLO + b_lane_off + nj * (16 * ROWB) + kb);
            }
            // set 1: Ahi x Bhi
#pragma unroll
            for (int mi = 0; mi < 4; mi++)
#pragma unroll
                for (int ni = 0; ni < 4; ni++)
                    mma_bf16(acc[mi][ni], ah[mi], bh[ni >> 1][(ni & 1) * 2], bh[ni >> 1][(ni & 1) * 2 + 1]);
            // set 2: Ahi x Blo
#pragma unroll
            for (int mi = 0; mi < 4; mi++)
#pragma unroll
                for (int ni = 0; ni < 4; ni++)
                    mma_bf16(acc[mi][ni], ah[mi], bl[ni >> 1][(ni & 1) * 2], bl[ni >> 1][(ni & 1) * 2 + 1]);
            // set 3: Alo x Bhi (Ahi dead -> regs reusable)
#pragma unroll
            for (int mi = 0; mi < 4; mi++)
                ldsm4(al[mi], stage + OFF_ALO + a_lane_off + mi * (16 * ROWB) + kb);
#pragma unroll
            for (int mi = 0; mi < 4; mi++)
#pragma unroll
                for (int ni = 0; ni < 4; ni++)
                    mma_bf16(acc[mi][ni], al[mi], bh[ni >> 1][(ni & 1) * 2], bh[ni >> 1][(ni & 1) * 2 + 1]);
        }

        if (more) storeA(next);
        CP_WAIT0();
        __syncthreads();
    }

    // ---- epilogue: D fragment -> C + bias ----
    const int gid = lane >> 2, tig = lane & 3;
#pragma unroll
    for (int mi = 0; mi < 4; mi++) {
        const int r0 = by * 128 + wm * 64 + mi * 16 + gid;
#pragma unroll
        for (int ni = 0; ni < 4; ni++) {
            const int col = bx * 256 + wn * 32 + ni * 8 + tig * 2;
            const float b0 = __ldg(bias + col), b1 = __ldg(bias + col + 1);
            float2 v0 = make_float2(acc[mi][ni][0] + b0, acc[mi][ni][1] + b1);
            float2 v1 = make_float2(acc[mi][ni][2] + b0, acc[mi][ni][3] + b1);
            *(float2*)(C + (size_t)r0 * GK + col) = v0;
            *(float2*)(C + (size_t)(r0 + 8) * GK + col) = v1;
        }
    }
}

// ---------------------------------------------------------------------------
// inv_norm[row] = rsqrt(max(sum(s[row]^2), 1e-10))
// ---------------------------------------------------------------------------
__global__ void rownorm_kernel(const float* __restrict__ s, float* __restrict__ inv) {
    const int row = blockIdx.x;
    const float* p = s + (size_t)row * D_DIM;
    float sum = 0.0f;
    for (int k = threadIdx.x; k < D_DIM; k += 256) {
        float v = p[k];
        sum = fmaf(v, v, sum);
    }
#pragma unroll
    for (int off = 16; off > 0; off >>= 1)
        sum += __shfl_down_sync(0xFFFFFFFF, sum, off);
    __shared__ float warpsum[8];
    const int lane = threadIdx.x & 31, wid = threadIdx.x >> 5;
    if (lane == 0) warpsum[wid] = sum;
    __syncthreads();
    if (threadIdx.x == 0) {
        float t = 0.0f;
#pragma unroll
        for (int w = 0; w < 8; w++) t += warpsum[w];
        inv[row] = rsqrtf(fmaxf(t, 1e-10f));
    }
}

// ---------------------------------------------------------------------------
// Fused attention (unchanged from passing R3 kernel)
// ---------------------------------------------------------------------------
#define TQ 30
#define KC 32

__global__ __launch_bounds__(160)
void attention_kernel(const float* __restrict__ onehot,
                      float* __restrict__ out, int out_size) {
    __shared__ __align__(16) float qs[TQ][KC + 1];
    __shared__ __align__(16) float ssT[KC][SPE + 4];
    __shared__ __align__(16) float simT[TQ][SPE];
    __shared__ float invn[SPE];
    __shared__ int   lab[SPE];
    __shared__ float probsS[TQ][NCLS];

    const int t = blockIdx.x;
    const int e = blockIdx.y;
    const int tid = threadIdx.x;
    const int qbase = e * QPE + t * TQ;
    const int sbase = e * SPE;

    if (tid < SPE) {
        invn[tid] = g_inv[sbase + tid];
        const float* oh = onehot + (size_t)(e * SPE + tid) * NCLS;
        int l = 0;
        float best = oh[0];
#pragma unroll
        for (int c = 1; c < NCLS; c++) {
            float v = oh[c];
            if (v > best) { best = v; l = c; }
        }
        lab[tid] = l;
    }

    const int rg = tid / 25;
    const int cg = tid % 25;
    const bool active = tid < 150;

    float acc[5][4];
#pragma unroll
    for (int ii = 0; ii < 5; ii++)
#pragma unroll
        for (int jj = 0; jj < 4; jj++) acc[ii][jj] = 0.0f;

    for (int k0 = 0; k0 < D_DIM; k0 += KC) {
        __syncthreads();
        for (int idx = tid; idx < TQ * KC; idx += 160) {
            int i = idx / KC, kc = idx % KC;
            qs[i][kc] = g_q[(size_t)(qbase + i) * D_DIM + k0 + kc];
        }
        for (int idx = tid; idx < SPE * KC; idx += 160) {
            int r = idx / KC, kc = idx % KC;
            ssT[kc][r] = g_s[(size_t)(sbase + r) * D_DIM + k0 + kc];
        }
        __syncthreads();
        if (active) {
#pragma unroll 4
            for (int kc = 0; kc < KC; kc++) {
                float4 sv = *(const float4*)(&ssT[kc][cg * 4]);
                float q0 = qs[rg * 5 + 0][kc];
                float q1 = qs[rg * 5 + 1][kc];
                float q2 = qs[rg * 5 + 2][kc];
                float q3 = qs[rg * 5 + 3][kc];
                float q4 = qs[rg * 5 + 4][kc];
                acc[0][0] = fmaf(q0, sv.x, acc[0][0]);
                acc[0][1] = fmaf(q0, sv.y, acc[0][1]);
                acc[0][2] = fmaf(q0, sv.z, acc[0][2]);
                acc[0][3] = fmaf(q0, sv.w, acc[0][3]);
                acc[1][0] = fmaf(q1, sv.x, acc[1][0]);
                acc[1][1] = fmaf(q1, sv.y, acc[1][1]);
                acc[1][2] = fmaf(q1, sv.z, acc[1][2]);
                acc[1][3] = fmaf(q1, sv.w, acc[1][3]);
                acc[2][0] = fmaf(q2, sv.x, acc[2][0]);
                acc[2][1] = fmaf(q2, sv.y, acc[2][1]);
                acc[2][2] = fmaf(q2, sv.z, acc[2][2]);
                acc[2][3] = fmaf(q2, sv.w, acc[2][3]);
                acc[3][0] = fmaf(q3, sv.x, acc[3][0]);
                acc[3][1] = fmaf(q3, sv.y, acc[3][1]);
                acc[3][2] = fmaf(q3, sv.z, acc[3][2]);
                acc[3][3] = fmaf(q3, sv.w, acc[3][3]);
                acc[4][0] = fmaf(q4, sv.x, acc[4][0]);
                acc[4][1] = fmaf(q4, sv.y, acc[4][1]);
                acc[4][2] = fmaf(q4, sv.z, acc[4][2]);
                acc[4][3] = fmaf(q4, sv.w, acc[4][3]);
            }
        }
    }
    __syncthreads();
    if (active) {
#pragma unroll
        for (int ii = 0; ii < 5; ii++)
#pragma unroll
            for (int jj = 0; jj < 4; jj++)
                simT[rg * 5 + ii][cg * 4 + jj] = acc[ii][jj] * invn[cg * 4 + jj];
    }
    __syncthreads();

    if (tid < TQ) {
        const int row = tid;
        float m = -1e30f;
#pragma unroll 4
        for (int ss = 0; ss < SPE; ss++) m = fmaxf(m, simT[row][ss]);
        float* p = probsS[row];
#pragma unroll
        for (int c = 0; c < NCLS; c++) p[c] = 0.0f;
        float sum = 0.0f;
        for (int ss = 0; ss < SPE; ss++) {
            float w = expf(simT[row][ss] - m);
            sum += w;
            p[lab[ss]] += w;
        }
        const float invsum = 1.0f / sum;
        const int grow = qbase + row;
        int bestc = 0;
        float bestv = p[0];
#pragma unroll
        for (int c = 0; c < NCLS; c++) {
            float v = p[c] * invsum;
            out[(size_t)grow * NCLS + c] = v;
            if (p[c] > bestv) { bestv = p[c]; bestc = c; }
        }
        if (out_size >= NQRY * NCLS + NQRY)
            out[NQRY * NCLS + grow] = (float)bestc;
    }
}

// ---------------------------------------------------------------------------
extern "C" void kernel_launch(void* const* d_in, const int* in_sizes, int n_in,
                              void* d_out, int out_size) {
    const float* support = (const float*)d_in[0];
    const float* query   = (const float*)d_in[1];
    const float* onehot  = (const float*)d_in[2];
    const float* W       = (const float*)d_in[3];
    const float* b       = (const float*)d_in[4];
    float* out = (float*)d_out;

    float *ps, *pq, *pinv;
    __nv_bfloat16 *whi, *wlo;
    cudaGetSymbolAddress((void**)&ps, g_s);
    cudaGetSymbolAddress((void**)&pq, g_q);
    cudaGetSymbolAddress((void**)&pinv, g_inv);
    cudaGetSymbolAddress((void**)&whi, g_wt_hi);
    cudaGetSymbolAddress((void**)&wlo, g_wt_lo);

    cudaFuncSetAttribute(gemm_mma, cudaFuncAttributeMaxDynamicSharedMemorySize, GEMM_SMEM);

    // W transpose + bf16 split
    wsplit_kernel<<<dim3(D_DIM / 32, D_DIM / 32), 256>>>(W, whi, wlo);

    // encoder GEMMs on tensor cores (split-bf16 via mma.sync)
    gemm_mma<<<dim3(D_DIM / 256, NSUP / 128), 512, GEMM_SMEM>>>(support, whi, wlo, b, ps);
    gemm_mma<<<dim3(D_DIM / 256, NQRY / 128), 512, GEMM_SMEM>>>(query, whi, wlo, b, pq);

    // support inverse norms
    rownorm_kernel<<<NSUP, 256>>>(ps, pinv);

    // fused attention / softmax / classify
    dim3 ga(QPE / TQ, NEP);
    attention_kernel<<<ga, 160>>>(onehot, out, out_size);
}

// round 7
// speedup vs baseline: 6.3011x; 2.5554x over previous
#include <cuda_runtime.h>
#include <cuda_bf16.h>
#include <math.h>
#include <stdint.h>

// Problem constants (fixed by reference setup_inputs):
// B=64, C=20, K=5, Q=15, D=H=2048
#define D_DIM 2048
#define GK    2048
#define NSUP  6400
#define NQRY  19200
#define NEP   64
#define SPE   100
#define QPE   300
#define NCLS  20

// Scratch (device globals: allocation-free per harness rules)
__device__ __nv_bfloat16 g_w_hi[GK * GK];     // W split hi  [k][n]
__device__ __nv_bfloat16 g_w_lo[GK * GK];
__device__ __nv_bfloat16 g_m_hi[GK * GK];     // M = W W^T split hi [i][j]
__device__ __nv_bfloat16 g_m_lo[GK * GK];
__device__ __nv_bfloat16 g_z_hi[NSUP * GK];   // Z = Xs M split hi [s][k]
__device__ __nv_bfloat16 g_z_lo[NSUP * GK];
__device__ float g_u[GK];                      // u = W b
__device__ float g_bb[1];                      // b.b
__device__ float g_ds[NSUP];                   // d_j = x_j . u
__device__ float g_dq[NQRY];                   // d_i = x_i . u
__device__ float g_inv[NSUP];                  // inv support norms

// ---------------------------------------------------------------------------
// PTX helpers (plain sm_80+ only — legal at compute_103 non-'a')
// ---------------------------------------------------------------------------
__device__ __forceinline__ uint32_t smem_u32(const void* p) {
    uint32_t a;
    asm("{ .reg .u64 t; cvta.to.shared.u64 t, %1; cvt.u32.u64 %0, t; }" : "=r"(a) : "l"(p));
    return a;
}
__device__ __forceinline__ void ldsm4(uint32_t* r, uint32_t addr) {
    asm volatile("ldmatrix.sync.aligned.m8n8.x4.shared.b16 {%0,%1,%2,%3}, [%4];"
                 : "=r"(r[0]), "=r"(r[1]), "=r"(r[2]), "=r"(r[3]) : "r"(addr));
}
__device__ __forceinline__ void mma_bf16(float* d, const uint32_t* a, uint32_t b0, uint32_t b1) {
    asm volatile("mma.sync.aligned.m16n8k16.row.col.f32.bf16.bf16.f32 "
                 "{%0,%1,%2,%3}, {%4,%5,%6,%7}, {%8,%9}, {%0,%1,%2,%3};"
                 : "+f"(d[0]), "+f"(d[1]), "+f"(d[2]), "+f"(d[3])
                 : "r"(a[0]), "r"(a[1]), "r"(a[2]), "r"(a[3]), "r"(b0), "r"(b1));
}
__device__ __forceinline__ void cp_async16(uint32_t dst, const void* src) {
    asm volatile("cp.async.ca.shared.global [%0], [%1], 16;" :: "r"(dst), "l"(src));
}
#define CP_COMMIT() asm volatile("cp.async.commit_group;" ::: "memory")
#define CP_WAIT0()  asm volatile("cp.async.wait_group 0;"  ::: "memory")

__device__ __forceinline__ void split2(float x, float y, uint32_t& h, uint32_t& l) {
    __nv_bfloat162 hh = __floats2bfloat162_rn(x, y);
    __nv_bfloat162 ll = __floats2bfloat162_rn(x - __low2float(hh), y - __high2float(hh));
    h = *reinterpret_cast<uint32_t*>(&hh);
    l = *reinterpret_cast<uint32_t*>(&ll);
}

// ---------------------------------------------------------------------------
// Elementwise split of W into bf16 hi/lo (no transpose needed)
// ---------------------------------------------------------------------------
__global__ __launch_bounds__(256)
void split_w(const float* __restrict__ W) {
    const size_t i = ((size_t)blockIdx.x * 256 + threadIdx.x) * 4;
    float4 v = *(const float4*)(W + i);
    uint32_t h0, l0, h1, l1;
    split2(v.x, v.y, h0, l0);
    split2(v.z, v.w, h1, l1);
    *(uint2*)(g_w_hi + i) = make_uint2(h0, h1);
    *(uint2*)(g_w_lo + i) = make_uint2(l0, l1);
}

// ---------------------------------------------------------------------------
// u[k] = sum_n W[k,n] b[n]   (one block per k row)
// ---------------------------------------------------------------------------
__global__ void wb_kernel(const float* __restrict__ W, const float* __restrict__ b) {
    const int row = blockIdx.x;
    const float* p = W + (size_t)row * GK;
    float sum = 0.0f;
    for (int k = threadIdx.x * 4; k < GK; k += 1024) {
        float4 w4 = *(const float4*)(p + k);
        float4 b4 = *(const float4*)(b + k);
        sum = fmaf(w4.x, b4.x, sum); sum = fmaf(w4.y, b4.y, sum);
        sum = fmaf(w4.z, b4.z, sum); sum = fmaf(w4.w, b4.w, sum);
    }
#pragma unroll
    for (int o = 16; o > 0; o >>= 1) sum += __shfl_down_sync(0xFFFFFFFF, sum, o);
    __shared__ float ws[8];
    if ((threadIdx.x & 31) == 0) ws[threadIdx.x >> 5] = sum;
    __syncthreads();
    if (threadIdx.x == 0) {
        float t = 0.0f;
#pragma unroll
        for (int w = 0; w < 8; w++) t += ws[w];
        g_u[row] = t;
    }
}

__global__ void bb_kernel(const float* __restrict__ b) {
    float sum = 0.0f;
    for (int k = threadIdx.x; k < GK; k += 256) { float v = b[k]; sum = fmaf(v, v, sum); }
#pragma unroll
    for (int o = 16; o > 0; o >>= 1) sum += __shfl_down_sync(0xFFFFFFFF, sum, o);
    __shared__ float ws[8];
    if ((threadIdx.x & 31) == 0) ws[threadIdx.x >> 5] = sum;
    __syncthreads();
    if (threadIdx.x == 0) {
        float t = 0.0f;
#pragma unroll
        for (int w = 0; w < 8; w++) t += ws[w];
        g_bb[0] = t;
    }
}

// ---------------------------------------------------------------------------
// d[row] = x_row . u   for query rows
// ---------------------------------------------------------------------------
__global__ void dq_kernel(const float* __restrict__ X) {
    const int row = blockIdx.x;
    const float* p = X + (size_t)row * GK;
    float sum = 0.0f;
    for (int k = threadIdx.x * 4; k < GK; k += 1024) {
        float4 x4 = *(const float4*)(p + k);
        float4 u4 = *(const float4*)(g_u + k);
        sum = fmaf(x4.x, u4.x, sum); sum = fmaf(x4.y, u4.y, sum);
        sum = fmaf(x4.z, u4.z, sum); sum = fmaf(x4.w, u4.w, sum);
    }
#pragma unroll
    for (int o = 16; o > 0; o >>= 1) sum += __shfl_down_sync(0xFFFFFFFF, sum, o);
    __shared__ float ws[8];
    if ((threadIdx.x & 31) == 0) ws[threadIdx.x >> 5] = sum;
    __syncthreads();
    if (threadIdx.x == 0) {
        float t = 0.0f;
#pragma unroll
        for (int w = 0; w < 8; w++) t += ws[w];
        g_dq[row] = t;
    }
}

// ---------------------------------------------------------------------------
// Support norms: |s_j|^2 = x_j.z_j + 2 x_j.u + bb ; also store d_j = x_j.u
// ---------------------------------------------------------------------------
__global__ void znorm_kernel(const float* __restrict__ Xs) {
    const int row = blockIdx.x;
    const float* x = Xs + (size_t)row * GK;
    const __nv_bfloat16* zh = g_z_hi + (size_t)row * GK;
    const __nv_bfloat16* zl = g_z_lo + (size_t)row * GK;
    float s1 = 0.0f, s2 = 0.0f;
    for (int k = threadIdx.x * 4; k < GK; k += 1024) {
        float4 x4 = *(const float4*)(x + k);
        float4 u4 = *(const float4*)(g_u + k);
        uint2 zh2 = *(const uint2*)(zh + k);
        uint2 zl2 = *(const uint2*)(zl + k);
        __nv_bfloat162 h0 = *(__nv_bfloat162*)&zh2.x, h1 = *(__nv_bfloat162*)&zh2.y;
        __nv_bfloat162 l0 = *(__nv_bfloat162*)&zl2.x, l1 = *(__nv_bfloat162*)&zl2.y;
        s1 = fmaf(__low2float(h0) + __low2float(l0), x4.x, s1);
        s1 = fmaf(__high2float(h0) + __high2float(l0), x4.y, s1);
        s1 = fmaf(__low2float(h1) + __low2float(l1), x4.z, s1);
        s1 = fmaf(__high2float(h1) + __high2float(l1), x4.w, s1);
        s2 = fmaf(x4.x, u4.x, s2); s2 = fmaf(x4.y, u4.y, s2);
        s2 = fmaf(x4.z, u4.z, s2); s2 = fmaf(x4.w, u4.w, s2);
    }
#pragma unroll
    for (int o = 16; o > 0; o >>= 1) {
        s1 += __shfl_down_sync(0xFFFFFFFF, s1, o);
        s2 += __shfl_down_sync(0xFFFFFFFF, s2, o);
    }
    __shared__ float w1[8], w2[8];
    if ((threadIdx.x & 31) == 0) { w1[threadIdx.x >> 5] = s1; w2[threadIdx.x >> 5] = s2; }
    __syncthreads();
    if (threadIdx.x == 0) {
        float t1 = 0.0f, t2 = 0.0f;
#pragma unroll
        for (int w = 0; w < 8; w++) { t1 += w1[w]; t2 += w2[w]; }
        float n2 = t1 + 2.0f * t2 + g_bb[0];
        g_inv[row] = rsqrtf(fmaxf(n2, 1e-10f));
        g_ds[row] = t2;
    }
}

// ---------------------------------------------------------------------------
// Split-bf16 GEMM (HMMA): O[M,2048] = A[M,2048] @ B^T  (B is [N][K] k-contig)
// 3 terms: Ahi*Bhi + Ahi*Blo + Alo*Bhi, fp32 acc. Output stored as bf16 hi/lo.
// BM=128, BN=256, BK=32, 512 threads (16 warps, warp tile 64x32).
// AFP32: A is fp32, split on the fly. Else A already split (bf16 hi/lo).
// ---------------------------------------------------------------------------
#define BKC 32
#define NCHUNK (GK / BKC)
#define ROWB 80
#define OFF_AHI 0
#define OFF_ALO (128 * ROWB)
#define OFF_BHI (2 * 128 * ROWB)
#define OFF_BLO (OFF_BHI + 256 * ROWB)
#define STAGEB  (OFF_BLO + 256 * ROWB)
#define GEMM_SMEM (2 * STAGEB)

template <bool AFP32>
__global__ __launch_bounds__(512, 1)
void gemm_split(const float* __restrict__ Afp,
                const __nv_bfloat16* __restrict__ AhiG, const __nv_bfloat16* __restrict__ AloG,
                const __nv_bfloat16* __restrict__ Bhi, const __nv_bfloat16* __restrict__ Blo,
                __nv_bfloat16* __restrict__ Ohi, __nv_bfloat16* __restrict__ Olo) {
    extern __shared__ __align__(128) char smem[];
    const uint32_t sb = smem_u32(smem);
    const int tid = threadIdx.x;
    const int lane = tid & 31, warp = tid >> 5;
    const int wm = warp & 1, wn = warp >> 1;
    const int bx = blockIdx.x, by = blockIdx.y;

    const float* Ab = AFP32 ? (Afp + (size_t)(by * 128) * GK) : nullptr;
    const __nv_bfloat16* AhiB = AFP32 ? nullptr : (AhiG + (size_t)(by * 128) * GK);
    const __nv_bfloat16* AloB = AFP32 ? nullptr : (AloG + (size_t)(by * 128) * GK);
    const size_t bn0 = (size_t)(bx * 256);

    // fp32-A fill tasks: 2 per thread
    const int ar0 = tid >> 3, ac0 = (tid & 7);
    const int ar1 = (tid + 512) >> 3, ac1 = ((tid + 512) & 7);
    // bf16-A fill tasks: 1 per thread per array
    const int xar = tid >> 2, xac = tid & 3;
    // B fill tasks: 2 per thread per array
    const int br0 = tid >> 2, bc0 = (tid & 3);
    const int br1 = (tid + 512) >> 2, bc1 = ((tid + 512) & 3);

    float4 a0, a1;

    auto loadA = [&](int k0) {
        a0 = *(const float4*)(Ab + (size_t)ar0 * GK + k0 + ac0 * 4);
        a1 = *(const float4*)(Ab + (size_t)ar1 * GK + k0 + ac1 * 4);
    };
    auto storeA = [&](uint32_t stoff) {
        uint32_t h0, l0, h1, l1;
        split2(a0.x, a0.y, h0, l0); split2(a0.z, a0.w, h1, l1);
        *(uint2*)(smem + stoff + OFF_AHI + ar0 * ROWB + ac0 * 8) = make_uint2(h0, h1);
        *(uint2*)(smem + stoff + OFF_ALO + ar0 * ROWB + ac0 * 8) = make_uint2(l0, l1);
        split2(a1.x, a1.y, h0, l0); split2(a1.z, a1.w, h1, l1);
        *(uint2*)(smem + stoff + OFF_AHI + ar1 * ROWB + ac1 * 8) = make_uint2(h0, h1);
        *(uint2*)(smem + stoff + OFF_ALO + ar1 * ROWB + ac1 * 8) = make_uint2(l0, l1);
    };
    auto cpA = [&](int k0, uint32_t stage) {
        cp_async16(stage + OFF_AHI + xar * ROWB + xac * 16, AhiB + (size_t)xar * GK + k0 + xac * 8);
        cp_async16(stage + OFF_ALO + xar * ROWB + xac * 16, AloB + (size_t)xar * GK + k0 + xac * 8);
    };
    auto loadB = [&](int k0, uint32_t stage) {
        cp_async16(stage + OFF_BHI + br0 * ROWB + bc0 * 16, Bhi + (bn0 + br0) * GK + k0 + bc0 * 8);
        cp_async16(stage + OFF_BLO + br0 * ROWB + bc0 * 16, Blo + (bn0 + br0) * GK + k0 + bc0 * 8);
        cp_async16(stage + OFF_BHI + br1 * ROWB + bc1 * 16, Bhi + (bn0 + br1) * GK + k0 + bc1 * 8);
        cp_async16(stage + OFF_BLO + br1 * ROWB + bc1 * 16, Blo + (bn0 + br1) * GK + k0 + bc1 * 8);
        CP_COMMIT();
    };

    const uint32_t a_lane_off = (uint32_t)((wm * 64 + (lane & 15)) * ROWB + (lane >> 4) * 16);
    const uint32_t b_lane_off = (uint32_t)((wn * 32 + ((lane >> 4) << 3) + (lane & 7)) * ROWB
                                           + ((lane >> 3) & 1) * 16);

    float acc[4][4][4];
#pragma unroll
    for (int mi = 0; mi < 4; mi++)
#pragma unroll
        for (int ni = 0; ni < 4; ni++)
#pragma unroll
            for (int j = 0; j < 4; j++) acc[mi][ni][j] = 0.0f;

    // prologue
    if (AFP32) { loadA(0); } else { cpA(0, sb); }
    loadB(0, sb);
    if (AFP32) storeA(0);
    CP_WAIT0();
    __syncthreads();

    for (int c = 0; c < NCHUNK; c++) {
        const uint32_t stoff = (uint32_t)((c & 1) * STAGEB);
        const uint32_t nxoff = (uint32_t)(((c + 1) & 1) * STAGEB);
        const bool more = (c + 1 < NCHUNK);
        if (more) {
            if (AFP32) loadA((c + 1) * BKC); else cpA((c + 1) * BKC, sb + nxoff);
            loadB((c + 1) * BKC, sb + nxoff);
        }

#pragma unroll
        for (int kk = 0; kk < 2; kk++) {
            const uint32_t kb = kk * 32;
            uint32_t ah[4][4], al[4][4], bh[2][4], bl[2][4];
#pragma unroll
            for (int mi = 0; mi < 4; mi++)
                ldsm4(ah[mi], sb + stoff + OFF_AHI + a_lane_off + mi * (16 * ROWB) + kb);
#pragma unroll
            for (int nj = 0; nj < 2; nj++) {
                ldsm4(bh[nj], sb + stoff + OFF_BHI + b_lane_off + nj * (16 * ROWB) + kb);
                ldsm4(bl[nj], sb + stoff + OFF_BLO + b_lane_off + nj * (16 * ROWB) + kb);
            }
#pragma unroll
            for (int mi = 0; mi < 4; mi++)
#pragma unroll
                for (int ni = 0; ni < 4; ni++)
                    mma_bf16(acc[mi][ni], ah[mi], bh[ni >> 1][(ni & 1) * 2], bh[ni >> 1][(ni & 1) * 2 + 1]);
#pragma unroll
            for (int mi = 0; mi < 4; mi++)
#pragma unroll
                for (int ni = 0; ni < 4; ni++)
                    mma_bf16(acc[mi][ni], ah[mi], bl[ni >> 1][(ni & 1) * 2], bl[ni >> 1][(ni & 1) * 2 + 1]);
#pragma unroll
            for (int mi = 0; mi < 4; mi++)
                ldsm4(al[mi], sb + stoff + OFF_ALO + a_lane_off + mi * (16 * ROWB) + kb);
#pragma unroll
            for (int mi = 0; mi < 4; mi++)
#pragma unroll
                for (int ni = 0; ni < 4; ni++)
                    mma_bf16(acc[mi][ni], al[mi], bh[ni >> 1][(ni & 1) * 2], bh[ni >> 1][(ni & 1) * 2 + 1]);
        }

        if (more && AFP32) storeA(nxoff);
        CP_WAIT0();
        __syncthreads();
    }

    // epilogue: split acc to bf16 hi/lo pairs (2 cols packed per uint32)
    const int gid = lane >> 2, tig = lane & 3;
#pragma unroll
    for (int mi = 0; mi < 4; mi++) {
        const int r0 = by * 128 + wm * 64 + mi * 16 + gid;
#pragma unroll
        for (int ni = 0; ni < 4; ni++) {
            const int col = bx * 256 + wn * 32 + ni * 8 + tig * 2;
            uint32_t h, l;
            split2(acc[mi][ni][0], acc[mi][ni][1], h, l);
            *(uint32_t*)(Ohi + (size_t)r0 * GK + col) = h;
            *(uint32_t*)(Olo + (size_t)r0 * GK + col) = l;
            split2(acc[mi][ni][2], acc[mi][ni][3], h, l);
            *(uint32_t*)(Ohi + (size_t)(r0 + 8) * GK + col) = h;
            *(uint32_t*)(Olo + (size_t)(r0 + 8) * GK + col) = l;
        }
    }
}

// ---------------------------------------------------------------------------
// Fused attention via HMMA: per (episode, 128-query tile):
//   sim[i][j] = (x_i.z_j + dq_i + ds_j + bb) * invn_j, softmax over j<100,
//   label-bucketed probs.
// 256 threads = 8 warps (4x2), warp tile 32x64. N padded to 128 (100 valid).
// ---------------------------------------------------------------------------
#define AT_ROWB 80
#define AT_AHI 0
#define AT_ALO (128 * AT_ROWB)
#define AT_BHI (2 * 128 * AT_ROWB)
#define AT_BLO (3 * 128 * AT_ROWB)
#define AT_STAGE (4 * 128 * AT_ROWB)          // 40960
#define AT_SIMT (2 * AT_STAGE)                // 81920
#define SIMW 132
#define AT_SMEM (AT_SIMT + 128 * SIMW * 4)    // 149504

__global__ __launch_bounds__(256, 1)
void attention_mma(const float* __restrict__ query, const float* __restrict__ onehot,
                   float* __restrict__ out, int out_size) {
    extern __shared__ __align__(128) char smem[];
    __shared__ float invn[128], dscol[128];
    __shared__ int lab[SPE];
    __shared__ float probsS[128][NCLS];
    const uint32_t sb = smem_u32(smem);
    const int tid = threadIdx.x, lane = tid & 31, warp = tid >> 5;
    const int wm = warp >> 1, wn = warp & 1;
    const int t = blockIdx.x, e = blockIdx.y;
    const int qbase = e * QPE + t * 128;
    const int nvalid = min(128, QPE - t * 128);
    const int sbase = e * SPE;

    if (tid < 128) {
        if (tid < SPE) { invn[tid] = g_inv[sbase + tid]; dscol[tid] = g_ds[sbase + tid]; }
        else           { invn[tid] = 0.0f; dscol[tid] = 0.0f; }
    }
    if (tid < SPE) {
        const float* oh = onehot + (size_t)(e * SPE + tid) * NCLS;
        int l = 0;
        float best = oh[0];
#pragma unroll
        for (int c = 1; c < NCLS; c++) { float v = oh[c]; if (v > best) { best = v; l = c; } }
        lab[tid] = l;
    }

    float4 areg[4];
    auto loadA = [&](int k0) {
#pragma unroll
        for (int i = 0; i < 4; i++) {
            int task = tid + i * 256;
            int row = task >> 3, c4 = task & 7;
            int qr = qbase + min(row, nvalid - 1);
            areg[i] = *(const float4*)(query + (size_t)qr * GK + k0 + c4 * 4);
        }
    };
    auto storeA = [&](uint32_t stoff) {
#pragma unroll
        for (int i = 0; i < 4; i++) {
            int task = tid + i * 256;
            int row = task >> 3, c4 = task & 7;
            uint32_t h0, l0, h1, l1;
            split2(areg[i].x, areg[i].y, h0, l0);
            split2(areg[i].z, areg[i].w, h1, l1);
            *(uint2*)(smem + stoff + AT_AHI + row * AT_ROWB + c4 * 8) = make_uint2(h0, h1);
            *(uint2*)(smem + stoff + AT_ALO + row * AT_ROWB + c4 * 8) = make_uint2(l0, l1);
        }
    };
    auto loadB = [&](int k0, uint32_t stage) {
#pragma unroll
        for (int i = 0; i < 2; i++) {
            int task = tid + i * 256;
            int row = task >> 2, ch = task & 3;
            int srow = sbase + min(row, SPE - 1);
            cp_async16(stage + AT_BHI + row * AT_ROWB + ch * 16, g_z_hi + (size_t)srow * GK + k0 + ch * 8);
            cp_async16(stage + AT_BLO + row * AT_ROWB + ch * 16, g_z_lo + (size_t)srow * GK + k0 + ch * 8);
        }
        CP_COMMIT();
    };

    const uint32_t a_lane_off = (uint32_t)((wm * 32 + (lane & 15)) * AT_ROWB + (lane >> 4) * 16);
    const uint32_t b_lane_off = (uint32_t)((wn * 64 + ((lane >> 4) << 3) + (lane & 7)) * AT_ROWB
                                           + ((lane >> 3) & 1) * 16);

    float acc[2][8][4];
#pragma unroll
    for (int mi = 0; mi < 2; mi++)
#pragma unroll
        for (int nf = 0; nf < 8; nf++)
#pragma unroll
            for (int j = 0; j < 4; j++) acc[mi][nf][j] = 0.0f;

    loadA(0);
    loadB(0, sb);
    storeA(0);
    CP_WAIT0();
    __syncthreads();

    for (int c = 0; c < NCHUNK; c++) {
        const uint32_t stoff = (uint32_t)((c & 1) * AT_STAGE);
        const uint32_t nxoff = (uint32_t)(((c + 1) & 1) * AT_STAGE);
        const bool more = (c + 1 < NCHUNK);
        if (more) { loadA((c + 1) * BKC); loadB((c + 1) * BKC, sb + nxoff); }

#pragma unroll
        for (int kk = 0; kk < 2; kk++) {
            const uint32_t kb = kk * 32;
            uint32_t ah[2][4], al[2][4], bh[4][4], bl[4][4];
#pragma unroll
            for (int mi = 0; mi < 2; mi++)
                ldsm4(ah[mi], sb + stoff + AT_AHI + a_lane_off + mi * (16 * AT_ROWB) + kb);
#pragma unroll
            for (int nj = 0; nj < 4; nj++) {
                ldsm4(bh[nj], sb + stoff + AT_BHI + b_lane_off + nj * (16 * AT_ROWB) + kb);
                ldsm4(bl[nj], sb + stoff + AT_BLO + b_lane_off + nj * (16 * AT_ROWB) + kb);
            }
#pragma unroll
            for (int mi = 0; mi < 2; mi++)
#pragma unroll
                for (int nf = 0; nf < 8; nf++)
                    mma_bf16(acc[mi][nf], ah[mi], bh[nf >> 1][(nf & 1) * 2], bh[nf >> 1][(nf & 1) * 2 + 1]);
#pragma unroll
            for (int mi = 0; mi < 2; mi++)
#pragma unroll
                for (int nf = 0; nf < 8; nf++)
                    mma_bf16(acc[mi][nf], ah[mi], bl[nf >> 1][(nf & 1) * 2], bl[nf >> 1][(nf & 1) * 2 + 1]);
#pragma unroll
            for (int mi = 0; mi < 2; mi++)
                ldsm4(al[mi], sb + stoff + AT_ALO + a_lane_off + mi * (16 * AT_ROWB) + kb);
#pragma unroll
            for (int mi = 0; mi < 2; mi++)
#pragma unroll
                for (int nf = 0; nf < 8; nf++)
                    mma_bf16(acc[mi][nf], al[mi], bh[nf >> 1][(nf & 1) * 2], bh[nf >> 1][(nf & 1) * 2 + 1]);
        }

        if (more) storeA(nxoff);
        CP_WAIT0();
        __syncthreads();
    }

    // epilogue: sim -> smem with bias corrections + column inv-norm scaling
    const int gid = lane >> 2, tig = lane & 3;
    const float bb = g_bb[0];
    float dqv[2][2];
#pragma unroll
    for (int mi = 0; mi < 2; mi++)
#pragma unroll
        for (int h = 0; h < 2; h++) {
            int row = wm * 32 + mi * 16 + gid + h * 8;
            dqv[mi][h] = g_dq[qbase + min(row, nvalid - 1)] + bb;
        }
    float* simT = (float*)(smem + AT_SIMT);
#pragma unroll
    for (int mi = 0; mi < 2; mi++) {
        const int r = wm * 32 + mi * 16 + gid;
#pragma unroll
        for (int nf = 0; nf < 8; nf++) {
            const int cb = wn * 64 + nf * 8 + tig * 2;
            simT[r * SIMW + cb]       = (acc[mi][nf][0] + dqv[mi][0] + dscol[cb])     * invn[cb];
            simT[r * SIMW + cb + 1]   = (acc[mi][nf][1] + dqv[mi][0] + dscol[cb + 1]) * invn[cb + 1];
            simT[(r + 8) * SIMW + cb]     = (acc[mi][nf][2] + dqv[mi][1] + dscol[cb])     * invn[cb];
            simT[(r + 8) * SIMW + cb + 1] = (acc[mi][nf][3] + dqv[mi][1] + dscol[cb + 1]) * invn[cb + 1];
        }
    }
    __syncthreads();

    // softmax + label bucketing, one thread per query row
    if (tid < nvalid) {
        const int r = tid;
        float m = -1e30f;
#pragma unroll 4
        for (int ss = 0; ss < SPE; ss++) m = fmaxf(m, simT[r * SIMW + ss]);
        float* p = probsS[r];
#pragma unroll
        for (int c = 0; c < NCLS; c++) p[c] = 0.0f;
        float sum = 0.0f;
        for (int ss = 0; ss < SPE; ss++) {
            float w = expf(simT[r * SIMW + ss] - m);
            sum += w;
            p[lab[ss]] += w;
        }
        const float invsum = 1.0f / sum;
        const int grow = qbase + r;
        int bestc = 0;
        float bestv = p[0];
#pragma unroll
        for (int c = 0; c < NCLS; c++) {
            float v = p[c] * invsum;
            out[(size_t)grow * NCLS + c] = v;
            if (p[c] > bestv) { bestv = p[c]; bestc = c; }
        }
        if (out_size >= NQRY * NCLS + NQRY)
            out[NQRY * NCLS + grow] = (float)bestc;
    }
}

// ---------------------------------------------------------------------------
extern "C" void kernel_launch(void* const* d_in, const int* in_sizes, int n_in,
                              void* d_out, int out_size) {
    const float* support = (const float*)d_in[0];
    const float* query   = (const float*)d_in[1];
    const float* onehot  = (const float*)d_in[2];
    const float* W       = (const float*)d_in[3];
    const float* b       = (const float*)d_in[4];
    float* out = (float*)d_out;

    __nv_bfloat16 *whi, *wlo, *mhi, *mlo, *zhi, *zlo;
    cudaGetSymbolAddress((void**)&whi, g_w_hi);
    cudaGetSymbolAddress((void**)&wlo, g_w_lo);
    cudaGetSymbolAddress((void**)&mhi, g_m_hi);
    cudaGetSymbolAddress((void**)&mlo, g_m_lo);
    cudaGetSymbolAddress((void**)&zhi, g_z_hi);
    cudaGetSymbolAddress((void**)&zlo, g_z_lo);

    cudaFuncSetAttribute(gemm_split<false>, cudaFuncAttributeMaxDynamicSharedMemorySize, GEMM_SMEM);
    cudaFuncSetAttribute(gemm_split<true>,  cudaFuncAttributeMaxDynamicSharedMemorySize, GEMM_SMEM);
    cudaFuncSetAttribute(attention_mma,     cudaFuncAttributeMaxDynamicSharedMemorySize, AT_SMEM);

    // 1. split W into bf16 hi/lo
    split_w<<<(GK * GK) / 1024, 256>>>(W);
    // 2. bias terms: u = W b, bb = b.b
    wb_kernel<<<GK, 256>>>(W, b);
    bb_kernel<<<1, 256>>>(b);
    // 3. M = W W^T (split-bf16 output)
    gemm_split<false><<<dim3(GK / 256, GK / 128), 512, GEMM_SMEM>>>(
        nullptr, whi, wlo, whi, wlo, mhi, mlo);
    // 4. Z = Xs M (fp32 A split on the fly; split-bf16 output)
    gemm_split<true><<<dim3(GK / 256, NSUP / 128), 512, GEMM_SMEM>>>(
        support, nullptr, nullptr, mhi, mlo, zhi, zlo);
    // 5. query bias dots d_i = x_i.u
    dq_kernel<<<NQRY, 256>>>(query);
    // 6. support norms + d_j
    znorm_kernel<<<NSUP, 256>>>(support);
    // 7. fused attention sim/softmax/classify on HMMA
    attention_mma<<<dim3(3, NEP), 256, AT_SMEM>>>(query, onehot, out, out_size);
}

// round 10
// speedup vs baseline: 6.7760x; 1.0754x over previous
#include <cuda_runtime.h>
#include <cuda_bf16.h>
#include <math.h>
#include <stdint.h>

// Problem constants: B=64, C=20, K=5, Q=15, D=H=2048
#define D_DIM 2048
#define GK    2048
#define NSUP  6400
#define NQRY  19200
#define NEP   64
#define SPE   100
#define QPE   300
#define NCLS  20

// Scratch (device globals: allocation-free per harness rules)
__device__ __nv_bfloat16 g_w_hi[GK * GK];     // W split hi  [k][n]
__device__ __nv_bfloat16 g_w_lo[GK * GK];
__device__ __nv_bfloat16 g_m_hi[GK * GK];     // M = W W^T split hi [i][j]
__device__ __nv_bfloat16 g_m_lo[GK * GK];
__device__ __nv_bfloat16 g_z_hi[NSUP * GK];   // Z = Xs M split hi [s][k]
__device__ __nv_bfloat16 g_z_lo[NSUP * GK];
__device__ float g_u[GK];                      // u = W b
__device__ float g_bb[1];                      // b.b
__device__ float g_ds[NSUP];                   // d_j = x_j . u
__device__ float g_dq[NQRY];                   // d_i = x_i . u
__device__ float g_inv[NSUP];                  // inv support norms

// ---------------------------------------------------------------------------
// PTX helpers (plain sm_80+ only — legal at compute_103 non-'a')
// ---------------------------------------------------------------------------
__device__ __forceinline__ uint32_t smem_u32(const void* p) {
    uint32_t a;
    asm("{ .reg .u64 t; cvta.to.shared.u64 t, %1; cvt.u32.u64 %0, t; }" : "=r"(a) : "l"(p));
    return a;
}
__device__ __forceinline__ void ldsm4(uint32_t* r, uint32_t addr) {
    asm volatile("ldmatrix.sync.aligned.m8n8.x4.shared.b16 {%0,%1,%2,%3}, [%4];"
                 : "=r"(r[0]), "=r"(r[1]), "=r"(r[2]), "=r"(r[3]) : "r"(addr));
}
__device__ __forceinline__ void mma_bf16(float* d, const uint32_t* a, uint32_t b0, uint32_t b1) {
    asm volatile("mma.sync.aligned.m16n8k16.row.col.f32.bf16.bf16.f32 "
                 "{%0,%1,%2,%3}, {%4,%5,%6,%7}, {%8,%9}, {%0,%1,%2,%3};"
                 : "+f"(d[0]), "+f"(d[1]), "+f"(d[2]), "+f"(d[3])
                 : "r"(a[0]), "r"(a[1]), "r"(a[2]), "r"(a[3]), "r"(b0), "r"(b1));
}
__device__ __forceinline__ void cp_async16(uint32_t dst, const void* src) {
    asm volatile("cp.async.ca.shared.global [%0], [%1], 16;" :: "r"(dst), "l"(src));
}
#define CP_COMMIT() asm volatile("cp.async.commit_group;" ::: "memory")
#define CP_WAIT0()  asm volatile("cp.async.wait_group 0;"  ::: "memory")

__device__ __forceinline__ void split2(float x, float y, uint32_t& h, uint32_t& l) {
    __nv_bfloat162 hh = __floats2bfloat162_rn(x, y);
    __nv_bfloat162 ll = __floats2bfloat162_rn(x - __low2float(hh), y - __high2float(hh));
    h = *reinterpret_cast<uint32_t*>(&hh);
    l = *reinterpret_cast<uint32_t*>(&ll);
}

// ---------------------------------------------------------------------------
// Elementwise split of W into bf16 hi/lo
// ---------------------------------------------------------------------------
__global__ __launch_bounds__(256)
void split_w(const float* __restrict__ W) {
    const size_t i = ((size_t)blockIdx.x * 256 + threadIdx.x) * 4;
    float4 v = *(const float4*)(W + i);
    uint32_t h0, l0, h1, l1;
    split2(v.x, v.y, h0, l0);
    split2(v.z, v.w, h1, l1);
    *(uint2*)(g_w_hi + i) = make_uint2(h0, h1);
    *(uint2*)(g_w_lo + i) = make_uint2(l0, l1);
}

// ---------------------------------------------------------------------------
// u[k] = sum_n W[k,n] b[n]
// ---------------------------------------------------------------------------
__global__ void wb_kernel(const float* __restrict__ W, const float* __restrict__ b) {
    const int row = blockIdx.x;
    const float* p = W + (size_t)row * GK;
    float sum = 0.0f;
    for (int k = threadIdx.x * 4; k < GK; k += 1024) {
        float4 w4 = *(const float4*)(p + k);
        float4 b4 = *(const float4*)(b + k);
        sum = fmaf(w4.x, b4.x, sum); sum = fmaf(w4.y, b4.y, sum);
        sum = fmaf(w4.z, b4.z, sum); sum = fmaf(w4.w, b4.w, sum);
    }
#pragma unroll
    for (int o = 16; o > 0; o >>= 1) sum += __shfl_down_sync(0xFFFFFFFF, sum, o);
    __shared__ float ws[8];
    if ((threadIdx.x & 31) == 0) ws[threadIdx.x >> 5] = sum;
    __syncthreads();
    if (threadIdx.x == 0) {
        float t = 0.0f;
#pragma unroll
        for (int w = 0; w < 8; w++) t += ws[w];
        g_u[row] = t;
    }
}

__global__ void bb_kernel(const float* __restrict__ b) {
    float sum = 0.0f;
    for (int k = threadIdx.x; k < GK; k += 256) { float v = b[k]; sum = fmaf(v, v, sum); }
#pragma unroll
    for (int o = 16; o > 0; o >>= 1) sum += __shfl_down_sync(0xFFFFFFFF, sum, o);
    __shared__ float ws[8];
    if ((threadIdx.x & 31) == 0) ws[threadIdx.x >> 5] = sum;
    __syncthreads();
    if (threadIdx.x == 0) {
        float t = 0.0f;
#pragma unroll
        for (int w = 0; w < 8; w++) t += ws[w];
        g_bb[0] = t;
    }
}

// ---------------------------------------------------------------------------
// d[row] = x_row . u   for query rows
// ---------------------------------------------------------------------------
__global__ void dq_kernel(const float* __restrict__ X) {
    const int row = blockIdx.x;
    const float* p = X + (size_t)row * GK;
    float sum = 0.0f;
    for (int k = threadIdx.x * 4; k < GK; k += 1024) {
        float4 x4 = *(const float4*)(p + k);
        float4 u4 = *(const float4*)(g_u + k);
        sum = fmaf(x4.x, u4.x, sum); sum = fmaf(x4.y, u4.y, sum);
        sum = fmaf(x4.z, u4.z, sum); sum = fmaf(x4.w, u4.w, sum);
    }
#pragma unroll
    for (int o = 16; o > 0; o >>= 1) sum += __shfl_down_sync(0xFFFFFFFF, sum, o);
    __shared__ float ws[8];
    if ((threadIdx.x & 31) == 0) ws[threadIdx.x >> 5] = sum;
    __syncthreads();
    if (threadIdx.x == 0) {
        float t = 0.0f;
#pragma unroll
        for (int w = 0; w < 8; w++) t += ws[w];
        g_dq[row] = t;
    }
}

// ---------------------------------------------------------------------------
// Support norms: |s_j|^2 = x_j.z_j + 2 x_j.u + bb ; also store d_j = x_j.u
// ---------------------------------------------------------------------------
__global__ void znorm_kernel(const float* __restrict__ Xs) {
    const int row = blockIdx.x;
    const float* x = Xs + (size_t)row * GK;
    const __nv_bfloat16* zh = g_z_hi + (size_t)row * GK;
    const __nv_bfloat16* zl = g_z_lo + (size_t)row * GK;
    float s1 = 0.0f, s2 = 0.0f;
    for (int k = threadIdx.x * 4; k < GK; k += 1024) {
        float4 x4 = *(const float4*)(x + k);
        float4 u4 = *(const float4*)(g_u + k);
        uint2 zh2 = *(const uint2*)(zh + k);
        uint2 zl2 = *(const uint2*)(zl + k);
        __nv_bfloat162 h0 = *(__nv_bfloat162*)&zh2.x, h1 = *(__nv_bfloat162*)&zh2.y;
        __nv_bfloat162 l0 = *(__nv_bfloat162*)&zl2.x, l1 = *(__nv_bfloat162*)&zl2.y;
        s1 = fmaf(__low2float(h0) + __low2float(l0), x4.x, s1);
        s1 = fmaf(__high2float(h0) + __high2float(l0), x4.y, s1);
        s1 = fmaf(__low2float(h1) + __low2float(l1), x4.z, s1);
        s1 = fmaf(__high2float(h1) + __high2float(l1), x4.w, s1);
        s2 = fmaf(x4.x, u4.x, s2); s2 = fmaf(x4.y, u4.y, s2);
        s2 = fmaf(x4.z, u4.z, s2); s2 = fmaf(x4.w, u4.w, s2);
    }
#pragma unroll
    for (int o = 16; o > 0; o >>= 1) {
        s1 += __shfl_down_sync(0xFFFFFFFF, s1, o);
        s2 += __shfl_down_sync(0xFFFFFFFF, s2, o);
    }
    __shared__ float w1[8], w2[8];
    if ((threadIdx.x & 31) == 0) { w1[threadIdx.x >> 5] = s1; w2[threadIdx.x >> 5] = s2; }
    __syncthreads();
    if (threadIdx.x == 0) {
        float t1 = 0.0f, t2 = 0.0f;
#pragma unroll
        for (int w = 0; w < 8; w++) { t1 += w1[w]; t2 += w2[w]; }
        float n2 = t1 + 2.0f * t2 + g_bb[0];
        g_inv[row] = rsqrtf(fmaxf(n2, 1e-10f));
        g_ds[row] = t2;
    }
}

// ---------------------------------------------------------------------------
// Split-bf16 GEMM (HMMA): O[M,2048] = A[M,2048] @ B^T  (B is [N][K] k-contig)
// 3 terms: Ahi*Bhi + Ahi*Blo + Alo*Bhi, fp32 acc. Output split bf16 hi/lo.
// BM=128, BN=128, BK=32, 256 threads (8 warps 2x4, warp tile 64x32).
// 2 CTAs/SM (regs 128*256*2 = 64K RF; smem 80KB*2 < 228KB).
// TRI: triangular grid skip (bx > by upper tiles skipped) for symmetric M.
// ---------------------------------------------------------------------------
#define BKC 32
#define NCHUNK (GK / BKC)
#define ROWB 80
#define OFF_AHI 0
#define OFF_ALO (128 * ROWB)
#define OFF_BHI (2 * 128 * ROWB)
#define OFF_BLO (3 * 128 * ROWB)
#define STAGEB  (4 * 128 * ROWB)          // 40960
#define GEMM_SMEM (2 * STAGEB)            // 81920

template <bool AFP32, bool TRI>
__global__ __launch_bounds__(256, 2)
void gemm_split(const float* __restrict__ Afp,
                const __nv_bfloat16* __restrict__ AhiG, const __nv_bfloat16* __restrict__ AloG,
                const __nv_bfloat16* __restrict__ Bhi, const __nv_bfloat16* __restrict__ Blo,
                __nv_bfloat16* __restrict__ Ohi, __nv_bfloat16* __restrict__ Olo) {
    const int bx = blockIdx.x, by = blockIdx.y;
    if (TRI && bx > by) return;          // upper-triangle tiles mirrored later
    extern __shared__ __align__(128) char smem[];
    const uint32_t sb = smem_u32(smem);
    const int tid = threadIdx.x;
    const int lane = tid & 31, warp = tid >> 5;
    const int wm = warp & 1, wn = warp >> 1;   // 2 x 4 warp grid, tile 64x32

    const float* Ab = AFP32 ? (Afp + (size_t)(by * 128) * GK) : nullptr;
    const __nv_bfloat16* AhiB = AFP32 ? nullptr : (AhiG + (size_t)(by * 128) * GK);
    const __nv_bfloat16* AloB = AFP32 ? nullptr : (AloG + (size_t)(by * 128) * GK);
    const size_t bn0 = (size_t)(bx * 128);

    float4 areg[4];
    auto loadA = [&](int k0) {
#pragma unroll
        for (int i = 0; i < 4; i++) {
            int task = tid + i * 256;
            areg[i] = *(const float4*)(Ab + (size_t)(task >> 3) * GK + k0 + (task & 7) * 4);
        }
    };
    auto storeA = [&](uint32_t stoff) {
#pragma unroll
        for (int i = 0; i < 4; i++) {
            int task = tid + i * 256;
            int row = task >> 3, c4 = task & 7;
            uint32_t h0, l0, h1, l1;
            split2(areg[i].x, areg[i].y, h0, l0);
            split2(areg[i].z, areg[i].w, h1, l1);
            *(uint2*)(smem + stoff + OFF_AHI + row * ROWB + c4 * 8) = make_uint2(h0, h1);
            *(uint2*)(smem + stoff + OFF_ALO + row * ROWB + c4 * 8) = make_uint2(l0, l1);
        }
    };
    auto cpA = [&](int k0, uint32_t stage) {
#pragma unroll
        for (int i = 0; i < 2; i++) {
            int task = tid + i * 256;
            int row = task >> 2, ch = task & 3;
            cp_async16(stage + OFF_AHI + row * ROWB + ch * 16, AhiB + (size_t)row * GK + k0 + ch * 8);
            cp_async16(stage + OFF_ALO + row * ROWB + ch * 16, AloB + (size_t)row * GK + k0 + ch * 8);
        }
    };
    auto loadB = [&](int k0, uint32_t stage) {
#pragma unroll
        for (int i = 0; i < 2; i++) {
            int task = tid + i * 256;
            int row = task >> 2, ch = task & 3;
            cp_async16(stage + OFF_BHI + row * ROWB + ch * 16, Bhi + (bn0 + row) * GK + k0 + ch * 8);
            cp_async16(stage + OFF_BLO + row * ROWB + ch * 16, Blo + (bn0 + row) * GK + k0 + ch * 8);
        }
        CP_COMMIT();
    };

    const uint32_t a_lane_off = (uint32_t)((wm * 64 + (lane & 15)) * ROWB + (lane >> 4) * 16);
    const uint32_t b_lane_off = (uint32_t)((wn * 32 + ((lane >> 4) << 3) + (lane & 7)) * ROWB
                                           + ((lane >> 3) & 1) * 16);

    float acc[4][4][4];
#pragma unroll
    for (int mi = 0; mi < 4; mi++)
#pragma unroll
        for (int ni = 0; ni < 4; ni++)
#pragma unroll
            for (int j = 0; j < 4; j++) acc[mi][ni][j] = 0.0f;

    if (AFP32) { loadA(0); } else { cpA(0, sb); }
    loadB(0, sb);
    if (AFP32) storeA(0);
    CP_WAIT0();
    __syncthreads();

    for (int c = 0; c < NCHUNK; c++) {
        const uint32_t stoff = (uint32_t)((c & 1) * STAGEB);
        const uint32_t nxoff = (uint32_t)(((c + 1) & 1) * STAGEB);
        const bool more = (c + 1 < NCHUNK);
        if (more) {
            if (AFP32) loadA((c + 1) * BKC); else cpA((c + 1) * BKC, sb + nxoff);
            loadB((c + 1) * BKC, sb + nxoff);
        }

#pragma unroll
        for (int kk = 0; kk < 2; kk++) {
            const uint32_t kb = kk * 32;
            uint32_t ah[4][4], al[4][4], bh[2][4], bl[2][4];
#pragma unroll
            for (int mi = 0; mi < 4; mi++)
                ldsm4(ah[mi], sb + stoff + OFF_AHI + a_lane_off + mi * (16 * ROWB) + kb);
#pragma unroll
            for (int nj = 0; nj < 2; nj++) {
                ldsm4(bh[nj], sb + stoff + OFF_BHI + b_lane_off + nj * (16 * ROWB) + kb);
                ldsm4(bl[nj], sb + stoff + OFF_BLO + b_lane_off + nj * (16 * ROWB) + kb);
            }
#pragma unroll
            for (int mi = 0; mi < 4; mi++)
#pragma unroll
                for (int ni = 0; ni < 4; ni++)
                    mma_bf16(acc[mi][ni], ah[mi], bh[ni >> 1][(ni & 1) * 2], bh[ni >> 1][(ni & 1) * 2 + 1]);
#pragma unroll
            for (int mi = 0; mi < 4; mi++)
#pragma unroll
                for (int ni = 0; ni < 4; ni++)
                    mma_bf16(acc[mi][ni], ah[mi], bl[ni >> 1][(ni & 1) * 2], bl[ni >> 1][(ni & 1) * 2 + 1]);
#pragma unroll
            for (int mi = 0; mi < 4; mi++)
                ldsm4(al[mi], sb + stoff + OFF_ALO + a_lane_off + mi * (16 * ROWB) + kb);
#pragma unroll
            for (int mi = 0; mi < 4; mi++)
#pragma unroll
                for (int ni = 0; ni < 4; ni++)
                    mma_bf16(acc[mi][ni], al[mi], bh[ni >> 1][(ni & 1) * 2], bh[ni >> 1][(ni & 1) * 2 + 1]);
        }

        if (more && AFP32) storeA(nxoff);
        CP_WAIT0();
        __syncthreads();
    }

    const int gid = lane >> 2, tig = lane & 3;
#pragma unroll
    for (int mi = 0; mi < 4; mi++) {
        const int r0 = by * 128 + wm * 64 + mi * 16 + gid;
#pragma unroll
        for (int ni = 0; ni < 4; ni++) {
            const int col = bx * 128 + wn * 32 + ni * 8 + tig * 2;
            uint32_t h, l;
            split2(acc[mi][ni][0], acc[mi][ni][1], h, l);
            *(uint32_t*)(Ohi + (size_t)r0 * GK + col) = h;
            *(uint32_t*)(Olo + (size_t)r0 * GK + col) = l;
            split2(acc[mi][ni][2], acc[mi][ni][3], h, l);
            *(uint32_t*)(Ohi + (size_t)(r0 + 8) * GK + col) = h;
            *(uint32_t*)(Olo + (size_t)(r0 + 8) * GK + col) = l;
        }
    }
}

// ---------------------------------------------------------------------------
// Mirror M's upper triangle from computed lower triangle (smem transpose).
// Target tile rows [a,a+32), cols [b,b+32), b >= a; source = tile (b rows, a cols).
// ---------------------------------------------------------------------------
__global__ __launch_bounds__(256)
void mirror_m() {
    if (blockIdx.x < blockIdx.y) return;
    const int a = blockIdx.y * 32, b = blockIdx.x * 32;
    __shared__ __nv_bfloat16 th[32][33], tl[32][33];
    const int tx = threadIdx.x & 31, ty = threadIdx.x >> 5;
#pragma unroll
    for (int i = 0; i < 4; i++) {
        int r = ty + i * 8;
        th[r][tx] = g_m_hi[(size_t)(b + r) * GK + a + tx];
        tl[r][tx] = g_m_lo[(size_t)(b + r) * GK + a + tx];
    }
    __syncthreads();
    const bool diag = (blockIdx.x == blockIdx.y);
#pragma unroll
    for (int i = 0; i < 4; i++) {
        int r = ty + i * 8;
        int row = a + r, col = b + tx;
        if (!diag || col > row) {
            g_m_hi[(size_t)row * GK + col] = th[tx][r];
            g_m_lo[(size_t)row * GK + col] = tl[tx][r];
        }
    }
}

// ---------------------------------------------------------------------------
// Fused attention via HMMA: grid (2, 64); block = 160 query rows (150 valid)
// x 128 support cols (100 valid). 320 threads = 10 warps (5m x 2n),
// warp tile 32x64. sim = (x.z + dq + ds + bb)*invn -> softmax -> buckets.
// ---------------------------------------------------------------------------
#define NV 150
#define AT_ROWB 80
#define AT_AHI 0
#define AT_ALO (160 * AT_ROWB)
#define AT_BHI (2 * 160 * AT_ROWB)
#define AT_BLO (AT_BHI + 128 * AT_ROWB)
#define AT_STAGE (AT_BLO + 128 * AT_ROWB)      // 46080
#define AT_SIMT (2 * AT_STAGE)                 // 92160
#define SIMW 132
#define AT_SMEM (AT_SIMT + 160 * SIMW * 4)     // 176640

__global__ __launch_bounds__(320, 1)
void attention_mma(const float* __restrict__ query, const float* __restrict__ onehot,
                   float* __restrict__ out, int out_size) {
    extern __shared__ __align__(128) char smem[];
    __shared__ float invn[128], dscol[128];
    __shared__ int lab[SPE];
    __shared__ float probsS[160][NCLS];
    const uint32_t sb = smem_u32(smem);
    const int tid = threadIdx.x, lane = tid & 31, warp = tid >> 5;
    const int wm = warp >> 1, wn = warp & 1;   // 5 x 2
    const int t = blockIdx.x, e = blockIdx.y;
    const int qbase = e * QPE + t * NV;
    const int sbase = e * SPE;

    if (tid < 128) {
        if (tid < SPE) { invn[tid] = g_inv[sbase + tid]; dscol[tid] = g_ds[sbase + tid]; }
        else           { invn[tid] = 0.0f; dscol[tid] = 0.0f; }
    }
    if (tid < SPE) {
        const float* oh = onehot + (size_t)(e * SPE + tid) * NCLS;
        int l = 0;
        float best = oh[0];
#pragma unroll
        for (int c = 1; c < NCLS; c++) { float v = oh[c]; if (v > best) { best = v; l = c; } }
        lab[tid] = l;
    }

    float4 areg[4];
    auto loadA = [&](int k0) {
#pragma unroll
        for (int i = 0; i < 4; i++) {
            int task = tid + i * 320;       // 1280 tasks = 160 rows x 8 chunks
            int row = task >> 3, c4 = task & 7;
            int qr = qbase + min(row, NV - 1);
            areg[i] = *(const float4*)(query + (size_t)qr * GK + k0 + c4 * 4);
        }
    };
    auto storeA = [&](uint32_t stoff) {
#pragma unroll
        for (int i = 0; i < 4; i++) {
            int task = tid + i * 320;
            int row = task >> 3, c4 = task & 7;
            uint32_t h0, l0, h1, l1;
            split2(areg[i].x, areg[i].y, h0, l0);
            split2(areg[i].z, areg[i].w, h1, l1);
            *(uint2*)(smem + stoff + AT_AHI + row * AT_ROWB + c4 * 8) = make_uint2(h0, h1);
            *(uint2*)(smem + stoff + AT_ALO + row * AT_ROWB + c4 * 8) = make_uint2(l0, l1);
        }
    };
    auto loadB = [&](int k0, uint32_t stage) {
        for (int idx = tid; idx < 512; idx += 320) {   // 128 rows x 4 chunks
            int row = idx >> 2, ch = idx & 3;
            int srow = sbase + min(row, SPE - 1);
            cp_async16(stage + AT_BHI + row * AT_ROWB + ch * 16, g_z_hi + (size_t)srow * GK + k0 + ch * 8);
            cp_async16(stage + AT_BLO + row * AT_ROWB + ch * 16, g_z_lo + (size_t)srow * GK + k0 + ch * 8);
        }
        CP_COMMIT();
    };

    const uint32_t a_lane_off = (uint32_t)((wm * 32 + (lane & 15)) * AT_ROWB + (lane >> 4) * 16);
    const uint32_t b_lane_off = (uint32_t)((wn * 64 + ((lane >> 4) << 3) + (lane & 7)) * AT_ROWB
                                           + ((lane >> 3) & 1) * 16);

    float acc[2][8][4];
#pragma unroll
    for (int mi = 0; mi < 2; mi++)
#pragma unroll
        for (int nf = 0; nf < 8; nf++)
#pragma unroll
            for (int j = 0; j < 4; j++) acc[mi][nf][j] = 0.0f;

    loadA(0);
    loadB(0, sb);
    storeA(0);
    CP_WAIT0();
    __syncthreads();

    for (int c = 0; c < NCHUNK; c++) {
        const uint32_t stoff = (uint32_t)((c & 1) * AT_STAGE);
        const uint32_t nxoff = (uint32_t)(((c + 1) & 1) * AT_STAGE);
        const bool more = (c + 1 < NCHUNK);
        if (more) { loadA((c + 1) * BKC); loadB((c + 1) * BKC, sb + nxoff); }

#pragma unroll
        for (int kk = 0; kk < 2; kk++) {
            const uint32_t kb = kk * 32;
            uint32_t ah[2][4], al[2][4], bh[4][4], bl[4][4];
#pragma unroll
            for (int mi = 0; mi < 2; mi++)
                ldsm4(ah[mi], sb + stoff + AT_AHI + a_lane_off + mi * (16 * AT_ROWB) + kb);
#pragma unroll
            for (int nj = 0; nj < 4; nj++) {
                ldsm4(bh[nj], sb + stoff + AT_BHI + b_lane_off + nj * (16 * AT_ROWB) + kb);
                ldsm4(bl[nj], sb + stoff + AT_BLO + b_lane_off + nj * (16 * AT_ROWB) + kb);
            }
#pragma unroll
            for (int mi = 0; mi < 2; mi++)
#pragma unroll
                for (int nf = 0; nf < 8; nf++)
                    mma_bf16(acc[mi][nf], ah[mi], bh[nf >> 1][(nf & 1) * 2], bh[nf >> 1][(nf & 1) * 2 + 1]);
#pragma unroll
            for (int mi = 0; mi < 2; mi++)
#pragma unroll
                for (int nf = 0; nf < 8; nf++)
                    mma_bf16(acc[mi][nf], ah[mi], bl[nf >> 1][(nf & 1) * 2], bl[nf >> 1][(nf & 1) * 2 + 1]);
#pragma unroll
            for (int mi = 0; mi < 2; mi++)
                ldsm4(al[mi], sb + stoff + AT_ALO + a_lane_off + mi * (16 * AT_ROWB) + kb);
#pragma unroll
            for (int mi = 0; mi < 2; mi++)
#pragma unroll
                for (int nf = 0; nf < 8; nf++)
                    mma_bf16(acc[mi][nf], al[mi], bh[nf >> 1][(nf & 1) * 2], bh[nf >> 1][(nf & 1) * 2 + 1]);
        }

        if (more) storeA(nxoff);
        CP_WAIT0();
        __syncthreads();
    }

    // epilogue: sim -> smem with bias corrections + column inv-norm scaling
    const int gid = lane >> 2, tig = lane & 3;
    const float bb = g_bb[0];
    float dqv[2][2];
#pragma unroll
    for (int mi = 0; mi < 2; mi++)
#pragma unroll
        for (int h = 0; h < 2; h++) {
            int row = wm * 32 + mi * 16 + gid + h * 8;
            dqv[mi][h] = g_dq[qbase + min(row, NV - 1)] + bb;
        }
    float* simT = (float*)(smem + AT_SIMT);
#pragma unroll
    for (int mi = 0; mi < 2; mi++) {
        const int r = wm * 32 + mi * 16 + gid;
#pragma unroll
        for (int nf = 0; nf < 8; nf++) {
            const int cb = wn * 64 + nf * 8 + tig * 2;
            simT[r * SIMW + cb]       = (acc[mi][nf][0] + dqv[mi][0] + dscol[cb])     * invn[cb];
            simT[r * SIMW + cb + 1]   = (acc[mi][nf][1] + dqv[mi][0] + dscol[cb + 1]) * invn[cb + 1];
            simT[(r + 8) * SIMW + cb]     = (acc[mi][nf][2] + dqv[mi][1] + dscol[cb])     * invn[cb];
            simT[(r + 8) * SIMW + cb + 1] = (acc[mi][nf][3] + dqv[mi][1] + dscol[cb + 1]) * invn[cb + 1];
        }
    }
    __syncthreads();

    if (tid < NV) {
        const int r = tid;
        float m = -1e30f;
#pragma unroll 4
        for (int ss = 0; ss < SPE; ss++) m = fmaxf(m, simT[r * SIMW + ss]);
        float* p = probsS[r];
#pragma unroll
        for (int c = 0; c < NCLS; c++) p[c] = 0.0f;
        float sum = 0.0f;
        for (int ss = 0; ss < SPE; ss++) {
            float w = expf(simT[r * SIMW + ss] - m);
            sum += w;
            p[lab[ss]] += w;
        }
        const float invsum = 1.0f / sum;
        const int grow = qbase + r;
        int bestc = 0;
        float bestv = p[0];
#pragma unroll
        for (int c = 0; c < NCLS; c++) {
            float v = p[c] * invsum;
            out[(size_t)grow * NCLS + c] = v;
            if (p[c] > bestv) { bestv = p[c]; bestc = c; }
        }
        if (out_size >= NQRY * NCLS + NQRY)
            out[NQRY * NCLS + grow] = (float)bestc;
    }
}

// ---------------------------------------------------------------------------
extern "C" void kernel_launch(void* const* d_in, const int* in_sizes, int n_in,
                              void* d_out, int out_size) {
    const float* support = (const float*)d_in[0];
    const float* query   = (const float*)d_in[1];
    const float* onehot  = (const float*)d_in[2];
    const float* W       = (const float*)d_in[3];
    const float* b       = (const float*)d_in[4];
    float* out = (float*)d_out;

    __nv_bfloat16 *whi, *wlo, *mhi, *mlo, *zhi, *zlo;
    cudaGetSymbolAddress((void**)&whi, g_w_hi);
    cudaGetSymbolAddress((void**)&wlo, g_w_lo);
    cudaGetSymbolAddress((void**)&mhi, g_m_hi);
    cudaGetSymbolAddress((void**)&mlo, g_m_lo);
    cudaGetSymbolAddress((void**)&zhi, g_z_hi);
    cudaGetSymbolAddress((void**)&zlo, g_z_lo);

    cudaFuncSetAttribute((const void*)gemm_split<false, true>,
                         cudaFuncAttributeMaxDynamicSharedMemorySize, GEMM_SMEM);
    cudaFuncSetAttribute((const void*)gemm_split<true, false>,
                         cudaFuncAttributeMaxDynamicSharedMemorySize, GEMM_SMEM);
    cudaFuncSetAttribute((const void*)attention_mma,
                         cudaFuncAttributeMaxDynamicSharedMemorySize, AT_SMEM);

    // 1. split W into bf16 hi/lo
    split_w<<<(GK * GK) / 1024, 256>>>(W);
    // 2. bias terms: u = W b, bb = b.b
    wb_kernel<<<GK, 256>>>(W, b);
    bb_kernel<<<1, 256>>>(b);
    // 3. M = W W^T, lower triangle only (symmetric), then mirror
    gemm_split<false, true><<<dim3(16, 16), 256, GEMM_SMEM>>>(
        nullptr, whi, wlo, whi, wlo, mhi, mlo);
    mirror_m<<<dim3(64, 64), 256>>>();
    // 4. Z = Xs M
    gemm_split<true, false><<<dim3(16, NSUP / 128), 256, GEMM_SMEM>>>(
        support, nullptr, nullptr, mhi, mlo, zhi, zlo);
    // 5. query bias dots
    dq_kernel<<<NQRY, 256>>>(query);
    // 6. support norms + d_j
    znorm_kernel<<<NSUP, 256>>>(support);
    // 7. fused attention sim/softmax/classify
    attention_mma<<<dim3(2, NEP), 320, AT_SMEM>>>(query, onehot, out, out_size);
}

// round 12
// speedup vs baseline: 7.7836x; 1.1487x over previous
#include <cuda_runtime.h>
#include <cuda_bf16.h>
#include <math.h>
#include <stdint.h>

// Problem constants: B=64, C=20, K=5, Q=15, D=H=2048
#define D_DIM 2048
#define GK    2048
#define NSUP  6400
#define NQRY  19200
#define NEP   64
#define SPE   100
#define QPE   300
#define NCLS  20

// Scratch (device globals: allocation-free per harness rules)
__device__ __nv_bfloat16 g_w_hi[GK * GK];     // W split hi  [k][n]
__device__ __nv_bfloat16 g_w_lo[GK * GK];
__device__ __nv_bfloat16 g_m_hi[GK * GK];     // M = W W^T split hi [i][j]
__device__ __nv_bfloat16 g_m_lo[GK * GK];
__device__ __nv_bfloat16 g_z_hi[NSUP * GK];   // Z = Xs M split hi [s][k]
__device__ __nv_bfloat16 g_z_lo[NSUP * GK];
__device__ float g_u[GK];                      // u = W b (fp32)
__device__ __nv_bfloat16 g_u_hi[GK];           // u split hi
__device__ __nv_bfloat16 g_u_lo[GK];           // u split lo
__device__ float g_bb[1];                      // b.b
__device__ float g_ds[NSUP];                   // d_j = x_j . u
__device__ float g_inv[NSUP];                  // inv support norms

// ---------------------------------------------------------------------------
// PTX helpers (plain sm_80+ only — legal at compute_103 non-'a')
// ---------------------------------------------------------------------------
__device__ __forceinline__ uint32_t smem_u32(const void* p) {
    uint32_t a;
    asm("{ .reg .u64 t; cvta.to.shared.u64 t, %1; cvt.u32.u64 %0, t; }" : "=r"(a) : "l"(p));
    return a;
}
__device__ __forceinline__ void ldsm4(uint32_t* r, uint32_t addr) {
    asm volatile("ldmatrix.sync.aligned.m8n8.x4.shared.b16 {%0,%1,%2,%3}, [%4];"
                 : "=r"(r[0]), "=r"(r[1]), "=r"(r[2]), "=r"(r[3]) : "r"(addr));
}
__device__ __forceinline__ void mma_bf16(float* d, const uint32_t* a, uint32_t b0, uint32_t b1) {
    asm volatile("mma.sync.aligned.m16n8k16.row.col.f32.bf16.bf16.f32 "
                 "{%0,%1,%2,%3}, {%4,%5,%6,%7}, {%8,%9}, {%0,%1,%2,%3};"
                 : "+f"(d[0]), "+f"(d[1]), "+f"(d[2]), "+f"(d[3])
                 : "r"(a[0]), "r"(a[1]), "r"(a[2]), "r"(a[3]), "r"(b0), "r"(b1));
}
__device__ __forceinline__ void cp_async16(uint32_t dst, const void* src) {
    asm volatile("cp.async.ca.shared.global [%0], [%1], 16;" :: "r"(dst), "l"(src));
}
#define CP_COMMIT() asm volatile("cp.async.commit_group;" ::: "memory")
#define CP_WAIT0()  asm volatile("cp.async.wait_group 0;"  ::: "memory")

__device__ __forceinline__ void split2(float x, float y, uint32_t& h, uint32_t& l) {
    __nv_bfloat162 hh = __floats2bfloat162_rn(x, y);
    __nv_bfloat162 ll = __floats2bfloat162_rn(x - __low2float(hh), y - __high2float(hh));
    h = *reinterpret_cast<uint32_t*>(&hh);
    l = *reinterpret_cast<uint32_t*>(&ll);
}

// ---------------------------------------------------------------------------
// Elementwise split of W into bf16 hi/lo
// ---------------------------------------------------------------------------
__global__ __launch_bounds__(256)
void split_w(const float* __restrict__ W) {
    const size_t i = ((size_t)blockIdx.x * 256 + threadIdx.x) * 4;
    float4 v = *(const float4*)(W + i);
    uint32_t h0, l0, h1, l1;
    split2(v.x, v.y, h0, l0);
    split2(v.z, v.w, h1, l1);
    *(uint2*)(g_w_hi + i) = make_uint2(h0, h1);
    *(uint2*)(g_w_lo + i) = make_uint2(l0, l1);
}

// ---------------------------------------------------------------------------
// u[k] = sum_n W[k,n] b[n]  (fp32 + split bf16)
// ---------------------------------------------------------------------------
__global__ void wb_kernel(const float* __restrict__ W, const float* __restrict__ b) {
    const int row = blockIdx.x;
    const float* p = W + (size_t)row * GK;
    float sum = 0.0f;
    for (int k = threadIdx.x * 4; k < GK; k += 1024) {
        float4 w4 = *(const float4*)(p + k);
        float4 b4 = *(const float4*)(b + k);
        sum = fmaf(w4.x, b4.x, sum); sum = fmaf(w4.y, b4.y, sum);
        sum = fmaf(w4.z, b4.z, sum); sum = fmaf(w4.w, b4.w, sum);
    }
#pragma unroll
    for (int o = 16; o > 0; o >>= 1) sum += __shfl_down_sync(0xFFFFFFFF, sum, o);
    __shared__ float ws[8];
    if ((threadIdx.x & 31) == 0) ws[threadIdx.x >> 5] = sum;
    __syncthreads();
    if (threadIdx.x == 0) {
        float t = 0.0f;
#pragma unroll
        for (int w = 0; w < 8; w++) t += ws[w];
        g_u[row] = t;
        __nv_bfloat16 h = __float2bfloat16_rn(t);
        g_u_hi[row] = h;
        g_u_lo[row] = __float2bfloat16_rn(t - __bfloat162float(h));
    }
}

__global__ void bb_kernel(const float* __restrict__ b) {
    float sum = 0.0f;
    for (int k = threadIdx.x; k < GK; k += 256) { float v = b[k]; sum = fmaf(v, v, sum); }
#pragma unroll
    for (int o = 16; o > 0; o >>= 1) sum += __shfl_down_sync(0xFFFFFFFF, sum, o);
    __shared__ float ws[8];
    if ((threadIdx.x & 31) == 0) ws[threadIdx.x >> 5] = sum;
    __syncthreads();
    if (threadIdx.x == 0) {
        float t = 0.0f;
#pragma unroll
        for (int w = 0; w < 8; w++) t += ws[w];
        g_bb[0] = t;
    }
}

// ---------------------------------------------------------------------------
// Support norms: |s_j|^2 = x_j.z_j + 2 x_j.u + bb ; also store d_j = x_j.u
// ---------------------------------------------------------------------------
__global__ void znorm_kernel(const float* __restrict__ Xs) {
    const int row = blockIdx.x;
    const float* x = Xs + (size_t)row * GK;
    const __nv_bfloat16* zh = g_z_hi + (size_t)row * GK;
    const __nv_bfloat16* zl = g_z_lo + (size_t)row * GK;
    float s1 = 0.0f, s2 = 0.0f;
    for (int k = threadIdx.x * 4; k < GK; k += 1024) {
        float4 x4 = *(const float4*)(x + k);
        float4 u4 = *(const float4*)(g_u + k);
        uint2 zh2 = *(const uint2*)(zh + k);
        uint2 zl2 = *(const uint2*)(zl + k);
        __nv_bfloat162 h0 = *(__nv_bfloat162*)&zh2.x, h1 = *(__nv_bfloat162*)&zh2.y;
        __nv_bfloat162 l0 = *(__nv_bfloat162*)&zl2.x, l1 = *(__nv_bfloat162*)&zl2.y;
        s1 = fmaf(__low2float(h0) + __low2float(l0), x4.x, s1);
        s1 = fmaf(__high2float(h0) + __high2float(l0), x4.y, s1);
        s1 = fmaf(__low2float(h1) + __low2float(l1), x4.z, s1);
        s1 = fmaf(__high2float(h1) + __high2float(l1), x4.w, s1);
        s2 = fmaf(x4.x, u4.x, s2); s2 = fmaf(x4.y, u4.y, s2);
        s2 = fmaf(x4.z, u4.z, s2); s2 = fmaf(x4.w, u4.w, s2);
    }
#pragma unroll
    for (int o = 16; o > 0; o >>= 1) {
        s1 += __shfl_down_sync(0xFFFFFFFF, s1, o);
        s2 += __shfl_down_sync(0xFFFFFFFF, s2, o);
    }
    __shared__ float w1[8], w2[8];
    if ((threadIdx.x & 31) == 0) { w1[threadIdx.x >> 5] = s1; w2[threadIdx.x >> 5] = s2; }
    __syncthreads();
    if (threadIdx.x == 0) {
        float t1 = 0.0f, t2 = 0.0f;
#pragma unroll
        for (int w = 0; w < 8; w++) { t1 += w1[w]; t2 += w2[w]; }
        float n2 = t1 + 2.0f * t2 + g_bb[0];
        g_inv[row] = rsqrtf(fmaxf(n2, 1e-10f));
        g_ds[row] = t2;
    }
}

// ---------------------------------------------------------------------------
// Split-bf16 GEMM (HMMA): O[M,2048] = A[M,2048] @ B^T  (B is [N][K] k-contig)
// 3 terms: Ahi*Bhi + Ahi*Blo + Alo*Bhi, fp32 acc. Output split bf16 hi/lo.
// BM=128, BN=128, BK=32, 256 threads (8 warps 2x4, warp tile 64x32).
// TRI: FLAT 1-D triangular grid (exactly 136 CTAs, bx <= by) -> 1 CTA/SM,
//      no placement imbalance from early-return blocks.
// ---------------------------------------------------------------------------
#define BKC 32
#define NCHUNK (GK / BKC)
#define ROWB 80
#define OFF_AHI 0
#define OFF_ALO (128 * ROWB)
#define OFF_BHI (2 * 128 * ROWB)
#define OFF_BLO (3 * 128 * ROWB)
#define STAGEB  (4 * 128 * ROWB)          // 40960
#define GEMM_SMEM (2 * STAGEB)            // 81920

template <bool AFP32, bool TRI>
__global__ __launch_bounds__(256, 2)
void gemm_split(const float* __restrict__ Afp,
                const __nv_bfloat16* __restrict__ AhiG, const __nv_bfloat16* __restrict__ AloG,
                const __nv_bfloat16* __restrict__ Bhi, const __nv_bfloat16* __restrict__ Blo,
                __nv_bfloat16* __restrict__ Ohi, __nv_bfloat16* __restrict__ Olo) {
    int bx, by;
    if (TRI) {
        // linear i -> (by, bx) with bx <= by; row by holds by+1 tiles
        int i = blockIdx.x;
        int t = 0;
        while ((t + 1) * (t + 2) / 2 <= i) t++;
        by = t;
        bx = i - t * (t + 1) / 2;
    } else {
        bx = blockIdx.x; by = blockIdx.y;
    }
    extern __shared__ __align__(128) char smem[];
    const uint32_t sb = smem_u32(smem);
    const int tid = threadIdx.x;
    const int lane = tid & 31, warp = tid >> 5;
    const int wm = warp & 1, wn = warp >> 1;   // 2 x 4 warp grid, tile 64x32

    const float* Ab = AFP32 ? (Afp + (size_t)(by * 128) * GK) : nullptr;
    const __nv_bfloat16* AhiB = AFP32 ? nullptr : (AhiG + (size_t)(by * 128) * GK);
    const __nv_bfloat16* AloB = AFP32 ? nullptr : (AloG + (size_t)(by * 128) * GK);
    const size_t bn0 = (size_t)(bx * 128);

    float4 areg[4];
    auto loadA = [&](int k0) {
#pragma unroll
        for (int i = 0; i < 4; i++) {
            int task = tid + i * 256;
            areg[i] = *(const float4*)(Ab + (size_t)(task >> 3) * GK + k0 + (task & 7) * 4);
        }
    };
    auto storeA = [&](uint32_t stoff) {
#pragma unroll
        for (int i = 0; i < 4; i++) {
            int task = tid + i * 256;
            int row = task >> 3, c4 = task & 7;
            uint32_t h0, l0, h1, l1;
            split2(areg[i].x, areg[i].y, h0, l0);
            split2(areg[i].z, areg[i].w, h1, l1);
            *(uint2*)(smem + stoff + OFF_AHI + row * ROWB + c4 * 8) = make_uint2(h0, h1);
            *(uint2*)(smem + stoff + OFF_ALO + row * ROWB + c4 * 8) = make_uint2(l0, l1);
        }
    };
    auto cpA = [&](int k0, uint32_t stage) {
#pragma unroll
        for (int i = 0; i < 2; i++) {
            int task = tid + i * 256;
            int row = task >> 2, ch = task & 3;
            cp_async16(stage + OFF_AHI + row * ROWB + ch * 16, AhiB + (size_t)row * GK + k0 + ch * 8);
            cp_async16(stage + OFF_ALO + row * ROWB + ch * 16, AloB + (size_t)row * GK + k0 + ch * 8);
        }
    };
    auto loadB = [&](int k0, uint32_t stage) {
#pragma unroll
        for (int i = 0; i < 2; i++) {
            int task = tid + i * 256;
            int row = task >> 2, ch = task & 3;
            cp_async16(stage + OFF_BHI + row * ROWB + ch * 16, Bhi + (bn0 + row) * GK + k0 + ch * 8);
            cp_async16(stage + OFF_BLO + row * ROWB + ch * 16, Blo + (bn0 + row) * GK + k0 + ch * 8);
        }
        CP_COMMIT();
    };

    const uint32_t a_lane_off = (uint32_t)((wm * 64 + (lane & 15)) * ROWB + (lane >> 4) * 16);
    const uint32_t b_lane_off = (uint32_t)((wn * 32 + ((lane >> 4) << 3) + (lane & 7)) * ROWB
                                           + ((lane >> 3) & 1) * 16);

    float acc[4][4][4];
#pragma unroll
    for (int mi = 0; mi < 4; mi++)
#pragma unroll
        for (int ni = 0; ni < 4; ni++)
#pragma unroll
            for (int j = 0; j < 4; j++) acc[mi][ni][j] = 0.0f;

    if (AFP32) { loadA(0); } else { cpA(0, sb); }
    loadB(0, sb);
    if (AFP32) storeA(0);
    CP_WAIT0();
    __syncthreads();

    for (int c = 0; c < NCHUNK; c++) {
        const uint32_t stoff = (uint32_t)((c & 1) * STAGEB);
        const uint32_t nxoff = (uint32_t)(((c + 1) & 1) * STAGEB);
        const bool more = (c + 1 < NCHUNK);
        if (more) {
            if (AFP32) loadA((c + 1) * BKC); else cpA((c + 1) * BKC, sb + nxoff);
            loadB((c + 1) * BKC, sb + nxoff);
        }

#pragma unroll
        for (int kk = 0; kk < 2; kk++) {
            const uint32_t kb = kk * 32;
            uint32_t ah[4][4], al[4][4], bh[2][4], bl[2][4];
#pragma unroll
            for (int mi = 0; mi < 4; mi++)
                ldsm4(ah[mi], sb + stoff + OFF_AHI + a_lane_off + mi * (16 * ROWB) + kb);
#pragma unroll
            for (int nj = 0; nj < 2; nj++) {
                ldsm4(bh[nj], sb + stoff + OFF_BHI + b_lane_off + nj * (16 * ROWB) + kb);
                ldsm4(bl[nj], sb + stoff + OFF_BLO + b_lane_off + nj * (16 * ROWB) + kb);
            }
#pragma unroll
            for (int mi = 0; mi < 4; mi++)
#pragma unroll
                for (int ni = 0; ni < 4; ni++)
                    mma_bf16(acc[mi][ni], ah[mi], bh[ni >> 1][(ni & 1) * 2], bh[ni >> 1][(ni & 1) * 2 + 1]);
#pragma unroll
            for (int mi = 0; mi < 4; mi++)
#pragma unroll
                for (int ni = 0; ni < 4; ni++)
                    mma_bf16(acc[mi][ni], ah[mi], bl[ni >> 1][(ni & 1) * 2], bl[ni >> 1][(ni & 1) * 2 + 1]);
#pragma unroll
            for (int mi = 0; mi < 4; mi++)
                ldsm4(al[mi], sb + stoff + OFF_ALO + a_lane_off + mi * (16 * ROWB) + kb);
#pragma unroll
            for (int mi = 0; mi < 4; mi++)
#pragma unroll
                for (int ni = 0; ni < 4; ni++)
                    mma_bf16(acc[mi][ni], al[mi], bh[ni >> 1][(ni & 1) * 2], bh[ni >> 1][(ni & 1) * 2 + 1]);
        }

        if (more && AFP32) storeA(nxoff);
        CP_WAIT0();
        __syncthreads();
    }

    const int gid = lane >> 2, tig = lane & 3;
#pragma unroll
    for (int mi = 0; mi < 4; mi++) {
        const int r0 = by * 128 + wm * 64 + mi * 16 + gid;
#pragma unroll
        for (int ni = 0; ni < 4; ni++) {
            const int col = bx * 128 + wn * 32 + ni * 8 + tig * 2;
            uint32_t h, l;
            split2(acc[mi][ni][0], acc[mi][ni][1], h, l);
            *(uint32_t*)(Ohi + (size_t)r0 * GK + col) = h;
            *(uint32_t*)(Olo + (size_t)r0 * GK + col) = l;
            split2(acc[mi][ni][2], acc[mi][ni][3], h, l);
            *(uint32_t*)(Ohi + (size_t)(r0 + 8) * GK + col) = h;
            *(uint32_t*)(Olo + (size_t)(r0 + 8) * GK + col) = l;
        }
    }
}

// ---------------------------------------------------------------------------
// Mirror M's upper triangle from computed lower triangle (smem transpose).
// ---------------------------------------------------------------------------
__global__ __launch_bounds__(256)
void mirror_m() {
    if (blockIdx.x < blockIdx.y) return;
    const int a = blockIdx.y * 32, b = blockIdx.x * 32;
    __shared__ __nv_bfloat16 th[32][33], tl[32][33];
    const int tx = threadIdx.x & 31, ty = threadIdx.x >> 5;
#pragma unroll
    for (int i = 0; i < 4; i++) {
        int r = ty + i * 8;
        th[r][tx] = g_m_hi[(size_t)(b + r) * GK + a + tx];
        tl[r][tx] = g_m_lo[(size_t)(b + r) * GK + a + tx];
    }
    __syncthreads();
    const bool diag = (blockIdx.x == blockIdx.y);
#pragma unroll
    for (int i = 0; i < 4; i++) {
        int r = ty + i * 8;
        int row = a + r, col = b + tx;
        if (!diag || col > row) {
            g_m_hi[(size_t)row * GK + col] = th[tx][r];
            g_m_lo[(size_t)row * GK + col] = tl[tx][r];
        }
    }
}

// ---------------------------------------------------------------------------
// Fused attention via HMMA: grid (2, 64); 160 query rows (150 valid) x 128
// support cols. Padding rows 100..127 of B hold u (split) -> acc col 127 is
// dq_i = x_i.u for free (one less pass over query). 320 threads = 10 warps
// (5m x 2n), warp tile 32x64. simT overlays the dead stage buffers.
// ---------------------------------------------------------------------------
#define NV 150
#define AT_ROWB 80
#define AT_AHI 0
#define AT_ALO (160 * AT_ROWB)
#define AT_BHI (2 * 160 * AT_ROWB)
#define AT_BLO (AT_BHI + 128 * AT_ROWB)
#define AT_STAGE (AT_BLO + 128 * AT_ROWB)      // 46080
#define SIMW 132
#define AT_SMEM (2 * AT_STAGE)                 // 92160 (simT overlays stages)

__global__ __launch_bounds__(320, 1)
void attention_mma(const float* __restrict__ query, const float* __restrict__ onehot,
                   float* __restrict__ out, int out_size) {
    extern __shared__ __align__(128) char smem[];
    __shared__ float invn[SPE], dscol[SPE];
    __shared__ int lab[SPE];
    __shared__ float probsS[160][NCLS];
    const uint32_t sb = smem_u32(smem);
    const int tid = threadIdx.x, lane = tid & 31, warp = tid >> 5;
    const int wm = warp >> 1, wn = warp & 1;   // 5 x 2
    const int t = blockIdx.x, e = blockIdx.y;
    const int qbase = e * QPE + t * NV;
    const int sbase = e * SPE;

    if (tid < SPE) {
        invn[tid] = g_inv[sbase + tid];
        dscol[tid] = g_ds[sbase + tid];
        const float* oh = onehot + (size_t)(e * SPE + tid) * NCLS;
        int l = 0;
        float best = oh[0];
#pragma unroll
        for (int c = 1; c < NCLS; c++) { float v = oh[c]; if (v > best) { best = v; l = c; } }
        lab[tid] = l;
    }

    float4 areg[4];
    auto loadA = [&](int k0) {
#pragma unroll
        for (int i = 0; i < 4; i++) {
            int task = tid + i * 320;       // 1280 tasks = 160 rows x 8 chunks
            int row = task >> 3, c4 = task & 7;
            int qr = qbase + min(row, NV - 1);
            areg[i] = *(const float4*)(query + (size_t)qr * GK + k0 + c4 * 4);
        }
    };
    auto storeA = [&](uint32_t stoff) {
#pragma unroll
        for (int i = 0; i < 4; i++) {
            int task = tid + i * 320;
            int row = task >> 3, c4 = task & 7;
            uint32_t h0, l0, h1, l1;
            split2(areg[i].x, areg[i].y, h0, l0);
            split2(areg[i].z, areg[i].w, h1, l1);
            *(uint2*)(smem + stoff + AT_AHI + row * AT_ROWB + c4 * 8) = make_uint2(h0, h1);
            *(uint2*)(smem + stoff + AT_ALO + row * AT_ROWB + c4 * 8) = make_uint2(l0, l1);
        }
    };
    auto loadB = [&](int k0, uint32_t stage) {
        for (int idx = tid; idx < 512; idx += 320) {   // 128 rows x 4 chunks
            int row = idx >> 2, ch = idx & 3;
            const __nv_bfloat16* srch;
            const __nv_bfloat16* srcl;
            if (row < SPE) {
                srch = g_z_hi + (size_t)(sbase + row) * GK + k0 + ch * 8;
                srcl = g_z_lo + (size_t)(sbase + row) * GK + k0 + ch * 8;
            } else {   // padding rows carry u -> acc col = x.u (dq)
                srch = g_u_hi + k0 + ch * 8;
                srcl = g_u_lo + k0 + ch * 8;
            }
            cp_async16(stage + AT_BHI + row * AT_ROWB + ch * 16, srch);
            cp_async16(stage + AT_BLO + row * AT_ROWB + ch * 16, srcl);
        }
        CP_COMMIT();
    };

    const uint32_t a_lane_off = (uint32_t)((wm * 32 + (lane & 15)) * AT_ROWB + (lane >> 4) * 16);
    const uint32_t b_lane_off = (uint32_t)((wn * 64 + ((lane >> 4) << 3) + (lane & 7)) * AT_ROWB
                                           + ((lane >> 3) & 1) * 16);

    float acc[2][8][4];
#pragma unroll
    for (int mi = 0; mi < 2; mi++)
#pragma unroll
        for (int nf = 0; nf < 8; nf++)
#pragma unroll
            for (int j = 0; j < 4; j++) acc[mi][nf][j] = 0.0f;

    loadA(0);
    loadB(0, sb);
    storeA(0);
    CP_WAIT0();
    __syncthreads();

    for (int c = 0; c < NCHUNK; c++) {
        const uint32_t stoff = (uint32_t)((c & 1) * AT_STAGE);
        const uint32_t nxoff = (uint32_t)(((c + 1) & 1) * AT_STAGE);
        const bool more = (c + 1 < NCHUNK);
        if (more) { loadA((c + 1) * BKC); loadB((c + 1) * BKC, sb + nxoff); }

#pragma unroll
        for (int kk = 0; kk < 2; kk++) {
            const uint32_t kb = kk * 32;
            uint32_t ah[2][4], al[2][4], bh[4][4], bl[4][4];
#pragma unroll
            for (int mi = 0; mi < 2; mi++)
                ldsm4(ah[mi], sb + stoff + AT_AHI + a_lane_off + mi * (16 * AT_ROWB) + kb);
#pragma unroll
            for (int nj = 0; nj < 4; nj++) {
                ldsm4(bh[nj], sb + stoff + AT_BHI + b_lane_off + nj * (16 * AT_ROWB) + kb);
                ldsm4(bl[nj], sb + stoff + AT_BLO + b_lane_off + nj * (16 * AT_ROWB) + kb);
            }
#pragma unroll
            for (int mi = 0; mi < 2; mi++)
#pragma unroll
                for (int nf = 0; nf < 8; nf++)
                    mma_bf16(acc[mi][nf], ah[mi], bh[nf >> 1][(nf & 1) * 2], bh[nf >> 1][(nf & 1) * 2 + 1]);
#pragma unroll
            for (int mi = 0; mi < 2; mi++)
#pragma unroll
                for (int nf = 0; nf < 8; nf++)
                    mma_bf16(acc[mi][nf], ah[mi], bl[nf >> 1][(nf & 1) * 2], bl[nf >> 1][(nf & 1) * 2 + 1]);
#pragma unroll
            for (int mi = 0; mi < 2; mi++)
                ldsm4(al[mi], sb + stoff + AT_ALO + a_lane_off + mi * (16 * AT_ROWB) + kb);
#pragma unroll
            for (int mi = 0; mi < 2; mi++)
#pragma unroll
                for (int nf = 0; nf < 8; nf++)
                    mma_bf16(acc[mi][nf], al[mi], bh[nf >> 1][(nf & 1) * 2], bh[nf >> 1][(nf & 1) * 2 + 1]);
        }

        if (more) storeA(nxoff);
        CP_WAIT0();
        __syncthreads();
    }

    // epilogue: write RAW acc into simT (overlays dead stage buffers)
    float* simT = (float*)smem;
    const int gid = lane >> 2, tig = lane & 3;
#pragma unroll
    for (int mi = 0; mi < 2; mi++) {
        const int r = wm * 32 + mi * 16 + gid;
#pragma unroll
        for (int nf = 0; nf < 8; nf++) {
            const int cb = wn * 64 + nf * 8 + tig * 2;
            simT[r * SIMW + cb]           = acc[mi][nf][0];
            simT[r * SIMW + cb + 1]       = acc[mi][nf][1];
            simT[(r + 8) * SIMW + cb]     = acc[mi][nf][2];
            simT[(r + 8) * SIMW + cb + 1] = acc[mi][nf][3];
        }
    }
    __syncthreads();

    // softmax + label bucketing; col 127 holds dq_i = x_i.u
    if (tid < NV) {
        const int r = tid;
        const float dqbb = simT[r * SIMW + 127] + g_bb[0];
        float m = -1e30f;
#pragma unroll 4
        for (int ss = 0; ss < SPE; ss++) {
            float v = (simT[r * SIMW + ss] + dqbb + dscol[ss]) * invn[ss];
            m = fmaxf(m, v);
        }
        float* p = probsS[r];
#pragma unroll
        for (int c = 0; c < NCLS; c++) p[c] = 0.0f;
        float sum = 0.0f;
        for (int ss = 0; ss < SPE; ss++) {
            float v = (simT[r * SIMW + ss] + dqbb + dscol[ss]) * invn[ss];
            float w = expf(v - m);
            sum += w;
            p[lab[ss]] += w;
        }
        const float invsum = 1.0f / sum;
        const int grow = qbase + r;
        int bestc = 0;
        float bestv = p[0];
#pragma unroll
        for (int c = 0; c < NCLS; c++) {
            float v = p[c] * invsum;
            out[(size_t)grow * NCLS + c] = v;
            if (p[c] > bestv) { bestv = p[c]; bestc = c; }
        }
        if (out_size >= NQRY * NCLS + NQRY)
            out[NQRY * NCLS + grow] = (float)bestc;
    }
}

// ---------------------------------------------------------------------------
extern "C" void kernel_launch(void* const* d_in, const int* in_sizes, int n_in,
                              void* d_out, int out_size) {
    const float* support = (const float*)d_in[0];
    const float* query   = (const float*)d_in[1];
    const float* onehot  = (const float*)d_in[2];
    const float* W       = (const float*)d_in[3];
    const float* b       = (const float*)d_in[4];
    float* out = (float*)d_out;

    __nv_bfloat16 *whi, *wlo, *mhi, *mlo, *zhi, *zlo;
    cudaGetSymbolAddress((void**)&whi, g_w_hi);
    cudaGetSymbolAddress((void**)&wlo, g_w_lo);
    cudaGetSymbolAddress((void**)&mhi, g_m_hi);
    cudaGetSymbolAddress((void**)&mlo, g_m_lo);
    cudaGetSymbolAddress((void**)&zhi, g_z_hi);
    cudaGetSymbolAddress((void**)&zlo, g_z_lo);

    cudaFuncSetAttribute((const void*)gemm_split<false, true>,
                         cudaFuncAttributeMaxDynamicSharedMemorySize, GEMM_SMEM);
    cudaFuncSetAttribute((const void*)gemm_split<true, false>,
                         cudaFuncAttributeMaxDynamicSharedMemorySize, GEMM_SMEM);
    cudaFuncSetAttribute((const void*)attention_mma,
                         cudaFuncAttributeMaxDynamicSharedMemorySize, AT_SMEM);

    // 1. split W into bf16 hi/lo
    split_w<<<(GK * GK) / 1024, 256>>>(W);
    // 2. bias terms: u = W b (fp32 + split), bb = b.b
    wb_kernel<<<GK, 256>>>(W, b);
    bb_kernel<<<1, 256>>>(b);
    // 3. M = W W^T, lower triangle on a FLAT 136-CTA grid, then mirror
    gemm_split<false, true><<<136, 256, GEMM_SMEM>>>(
        nullptr, whi, wlo, whi, wlo, mhi, mlo);
    mirror_m<<<dim3(64, 64), 256>>>();
    // 4. Z = Xs M
    gemm_split<true, false><<<dim3(16, NSUP / 128), 256, GEMM_SMEM>>>(
        support, nullptr, nullptr, mhi, mlo, zhi, zlo);
    // 5. support norms + d_j (query dots folded into attention via u-rows)
    znorm_kernel<<<NSUP, 256>>>(support);
    // 6. fused attention sim/softmax/classify
    attention_mma<<<dim3(2, NEP), 320, AT_SMEM>>>(query, onehot, out, out_size);
}